// round 3
// baseline (speedup 1.0000x reference)
#include <cuda_runtime.h>
#include <math_constants.h>

// Problem constants
#define T_TOK 32768     // B*N = 16*2048
#define D_DIM 1408
#define P_DIM 256
#define KC0 64
#define KC1 128
#define KC2 256

// GEMM tiling
#define BM 128
#define BN 64
#define BK 16

// ------------------- device scratch (static, no allocation) -------------------
static __device__ float  g_r[(size_t)T_TOK * P_DIM];        // residual (starts = z_proj), 33.5 MB
static __device__ float  g_S[(size_t)T_TOK * KC2];          // per-level scores, 33.5 MB
static __device__ float  g_ssr[T_TOK];                      // ||r||^2 per token (fp32, sequential)
static __device__ float  g_ssq[KC0 + KC1 + KC2];            // ||e_j||^2 (fp32, sequential)
static __device__ float  g_EW[(size_t)(KC0 + KC1 + KC2) * D_DIM];  // emb_cat @ W_out
static __device__ int    g_idx[3 * T_TOK];
static __device__ double g_losspart[3 * 4096];

// ------------------- GEMM1: z_proj = z @ W_in + b_in  (sequential-k fp32 FMA) ----
__global__ __launch_bounds__(256) void k_gemm1(const float* __restrict__ A,
                                               const float* __restrict__ W,
                                               const float* __restrict__ bias) {
    __shared__ float As[BK][BM + 4];
    __shared__ float Bs[BK][BN];
    const int tid = threadIdx.x;
    const int bm = blockIdx.y * BM;
    const int bn = blockIdx.x * BN;
    const int tr = (tid >> 4) << 3;
    const int tc = (tid & 15) << 2;

    float acc[8][4];
#pragma unroll
    for (int i = 0; i < 8; i++)
#pragma unroll
        for (int j = 0; j < 4; j++) acc[i][j] = 0.f;

    for (int k0 = 0; k0 < D_DIM; k0 += BK) {
#pragma unroll
        for (int i = 0; i < 2; i++) {
            int lid = tid * 2 + i;
            int ar = lid >> 2;
            int a4 = lid & 3;
            float4 v = *(const float4*)(A + (size_t)(bm + ar) * D_DIM + k0 + a4 * 4);
            As[a4 * 4 + 0][ar] = v.x;
            As[a4 * 4 + 1][ar] = v.y;
            As[a4 * 4 + 2][ar] = v.z;
            As[a4 * 4 + 3][ar] = v.w;
        }
        {
            int br = tid >> 4;
            int b4 = tid & 15;
            float4 v = *(const float4*)(W + (size_t)(k0 + br) * P_DIM + bn + b4 * 4);
            *(float4*)(&Bs[br][b4 * 4]) = v;
        }
        __syncthreads();
#pragma unroll
        for (int kk = 0; kk < BK; kk++) {   // strictly ascending k, single accumulator, FMA
            float4 b  = *(const float4*)(&Bs[kk][tc]);
            float4 a0 = *(const float4*)(&As[kk][tr]);
            float4 a1 = *(const float4*)(&As[kk][tr + 4]);
            float av[8] = {a0.x, a0.y, a0.z, a0.w, a1.x, a1.y, a1.z, a1.w};
            float bv[4] = {b.x, b.y, b.z, b.w};
#pragma unroll
            for (int i = 0; i < 8; i++)
#pragma unroll
                for (int j = 0; j < 4; j++) acc[i][j] = __fmaf_rn(av[i], bv[j], acc[i][j]);
        }
        __syncthreads();
    }
#pragma unroll
    for (int j = 0; j < 4; j++) {
        float bv = bias[bn + tc + j];
#pragma unroll
        for (int i = 0; i < 8; i++) acc[i][j] = __fadd_rn(acc[i][j], bv);
    }
#pragma unroll
    for (int i = 0; i < 8; i++) {
        float4 o = make_float4(acc[i][0], acc[i][1], acc[i][2], acc[i][3]);
        *(float4*)(g_r + (size_t)(bm + tr + i) * P_DIM + bn + tc) = o;
    }
}

// ------------------- ssq_j = sum(e_j * e_j)  (fp32: round products, sequential add) ----
__global__ __launch_bounds__(256) void k_ssqE(const float* __restrict__ e0,
                                              const float* __restrict__ e1,
                                              const float* __restrict__ e2) {
    int r = blockIdx.x * 256 + threadIdx.x;
    if (r >= KC0 + KC1 + KC2) return;
    const float* src = (r < KC0) ? (e0 + (size_t)r * P_DIM)
                     : (r < KC0 + KC1) ? (e1 + (size_t)(r - KC0) * P_DIM)
                                       : (e2 + (size_t)(r - KC0 - KC1) * P_DIM);
    float s = 0.f;
    for (int p = 0; p < P_DIM; p++) {
        float v = src[p];
        s = __fadd_rn(s, __fmul_rn(v, v));
    }
    g_ssq[r] = s;
}

// ------------------- ssr_t = sum(r_t * r_t)  (fp32: round products, sequential add) ----
__global__ __launch_bounds__(32) void k_ssr() {
    __shared__ float tile[32 * 257];
    const int tid = threadIdx.x;
    const size_t base = (size_t)blockIdx.x * 32;   // 1024 blocks x 32 tokens
    for (int i = tid; i < 32 * P_DIM; i += 32) {
        int row = i >> 8, col = i & 255;
        tile[row * 257 + col] = g_r[base * P_DIM + i];
    }
    __syncthreads();
    float s = 0.f;
    const float* rr = &tile[tid * 257];
    for (int p = 0; p < P_DIM; p++)
        s = __fadd_rn(s, __fmul_rn(rr[p], rr[p]));
    g_ssr[base + tid] = s;
}

// ------------------- S = r @ cb^T  (sequential-k fp32 FMA), K columns -------------------
template <int K>
__global__ __launch_bounds__(256) void k_gemmS(const float* __restrict__ cb) {
    __shared__ float As[BK][BM + 4];
    __shared__ float Bs[BK][BN + 4];
    const int tid = threadIdx.x;
    const int bm = blockIdx.y * BM;
    const int bn = blockIdx.x * BN;
    const int tr = (tid >> 4) << 3;
    const int tc = (tid & 15) << 2;

    float acc[8][4];
#pragma unroll
    for (int i = 0; i < 8; i++)
#pragma unroll
        for (int j = 0; j < 4; j++) acc[i][j] = 0.f;

    for (int k0 = 0; k0 < P_DIM; k0 += BK) {
#pragma unroll
        for (int i = 0; i < 2; i++) {
            int lid = tid * 2 + i;
            int ar = lid >> 2;
            int a4 = lid & 3;
            float4 v = *(const float4*)(g_r + (size_t)(bm + ar) * P_DIM + k0 + a4 * 4);
            As[a4 * 4 + 0][ar] = v.x;
            As[a4 * 4 + 1][ar] = v.y;
            As[a4 * 4 + 2][ar] = v.z;
            As[a4 * 4 + 3][ar] = v.w;
        }
        {
            int jr = tid >> 2;      // 0..63 codebook row within block
            int j4 = tid & 3;
            float4 v = *(const float4*)(cb + (size_t)(bn + jr) * P_DIM + k0 + j4 * 4);
            Bs[j4 * 4 + 0][jr] = v.x;
            Bs[j4 * 4 + 1][jr] = v.y;
            Bs[j4 * 4 + 2][jr] = v.z;
            Bs[j4 * 4 + 3][jr] = v.w;
        }
        __syncthreads();
#pragma unroll
        for (int kk = 0; kk < BK; kk++) {   // strictly ascending k, single accumulator, FMA
            float4 b  = *(const float4*)(&Bs[kk][tc]);
            float4 a0 = *(const float4*)(&As[kk][tr]);
            float4 a1 = *(const float4*)(&As[kk][tr + 4]);
            float av[8] = {a0.x, a0.y, a0.z, a0.w, a1.x, a1.y, a1.z, a1.w};
            float bv[4] = {b.x, b.y, b.z, b.w};
#pragma unroll
            for (int i = 0; i < 8; i++)
#pragma unroll
                for (int j = 0; j < 4; j++) acc[i][j] = __fmaf_rn(av[i], bv[j], acc[i][j]);
        }
        __syncthreads();
    }
#pragma unroll
    for (int i = 0; i < 8; i++) {
        float4 o = make_float4(acc[i][0], acc[i][1], acc[i][2], acc[i][3]);
        *(float4*)(g_S + (size_t)(bm + tr + i) * K + bn + tc) = o;
    }
}

// ------------------- per-level pick: d = (ssr - 2*S) + ssq ; argmin first-index ------
// Then residual update r -= e[idx] (fp32, identical op to reference) + fp64 loss partial.
template <int K, int LVL, int SSQ_OFF>
__global__ __launch_bounds__(256) void k_pick(const float* __restrict__ cb,
                                              float* __restrict__ out_idxf) {
    const int warp = threadIdx.x >> 5;
    const int lane = threadIdx.x & 31;
    const int t = blockIdx.x * 8 + warp;

    const float ssr = g_ssr[t];
    const float* Srow = g_S + (size_t)t * K;

    float best = CUDART_INF_F;
    int bi = 0x7fffffff;
#pragma unroll
    for (int kc = 0; kc < K / 32; kc++) {   // ascending j within lane
        int j = kc * 32 + lane;
        // reference rounding: (ssr - 2*S) then + ssq ; 2*S is exact
        float d = __fadd_rn(__fsub_rn(ssr, 2.0f * Srow[j]), g_ssq[SSQ_OFF + j]);
        if (d < best) { best = d; bi = j; }     // ties keep earlier (lower j)
    }
#pragma unroll
    for (int o = 16; o; o >>= 1) {              // cross-lane: first-min (lowest index on tie)
        float od = __shfl_xor_sync(0xffffffffu, best, o);
        int   oi = __shfl_xor_sync(0xffffffffu, bi, o);
        if (od < best || (od == best && oi < bi)) { best = od; bi = oi; }
    }
    const int idx = bi;

    // residual update + fp64 loss partial of new residual
    const float* er = cb + (size_t)idx * P_DIM;
    float* rrow = g_r + (size_t)t * P_DIM;
    double ls = 0.0;
#pragma unroll
    for (int k = 0; k < 8; k++) {
        int p = lane + 32 * k;
        float nv = __fsub_rn(rrow[p], er[p]);
        rrow[p] = nv;
        ls += (double)nv * (double)nv;
    }
#pragma unroll
    for (int o = 16; o; o >>= 1) ls += __shfl_xor_sync(0xffffffffu, ls, o);

    __shared__ double lsm[8];
    if (lane == 0) {
        g_idx[LVL * T_TOK + t] = idx;
        out_idxf[LVL * T_TOK + t] = (float)idx;
        lsm[warp] = ls;
    }
    __syncthreads();
    if (threadIdx.x == 0) {
        double tot = 0.0;
#pragma unroll
        for (int i = 0; i < 8; i++) tot += lsm[i];
        g_losspart[LVL * 4096 + blockIdx.x] = tot;
    }
}

// ------------------- loss reduce -------------------
__global__ __launch_bounds__(256) void k_lossred(float* __restrict__ out_loss) {
    __shared__ double sm[256];
    double s = 0.0;
    for (int i = threadIdx.x; i < 3 * 4096; i += 256) s += g_losspart[i];
    sm[threadIdx.x] = s;
    __syncthreads();
    for (int o = 128; o; o >>= 1) {
        if (threadIdx.x < o) sm[threadIdx.x] += sm[threadIdx.x + o];
        __syncthreads();
    }
    if (threadIdx.x == 0)
        *out_loss = (float)(sm[0] * (0.25 / (3.0 * (double)T_TOK * (double)P_DIM)));
}

// ------------------- EW = emb_cat @ W_out  [448,1408] -------------------
__global__ __launch_bounds__(256) void k_ew(const float* __restrict__ e0,
                                            const float* __restrict__ e1,
                                            const float* __restrict__ e2,
                                            const float* __restrict__ Wout) {
    __shared__ float a[8][P_DIM];
    const int rbase = blockIdx.x * 8;
    for (int i = threadIdx.x; i < 8 * P_DIM; i += 256) {
        int r = rbase + i / P_DIM;
        int p = i % P_DIM;
        const float* s = (r < KC0) ? (e0 + (size_t)r * P_DIM)
                       : (r < KC0 + KC1) ? (e1 + (size_t)(r - KC0) * P_DIM)
                                         : (e2 + (size_t)(r - KC0 - KC1) * P_DIM);
        a[i / P_DIM][p] = s[p];
    }
    __syncthreads();
    for (int c = threadIdx.x; c < D_DIM; c += 256) {
        float acc[8] = {0.f, 0.f, 0.f, 0.f, 0.f, 0.f, 0.f, 0.f};
        for (int p = 0; p < P_DIM; p++) {
            float w = Wout[(size_t)p * D_DIM + c];
#pragma unroll
            for (int r = 0; r < 8; r++) acc[r] = __fmaf_rn(a[r][p], w, acc[r]);
        }
#pragma unroll
        for (int r = 0; r < 8; r++) g_EW[(size_t)(rbase + r) * D_DIM + c] = acc[r];
    }
}

// ------------------- output gather: z_q_out = EW0[i0]+EW1[i1]+EW2[i2]+b_out ------------
__global__ __launch_bounds__(352) void k_out(const float* __restrict__ bout,
                                             float* __restrict__ out) {
    const int t = blockIdx.x;
    const int i0 = g_idx[t];
    const int i1 = g_idx[T_TOK + t];
    const int i2 = g_idx[2 * T_TOK + t];
    const float4* r0 = (const float4*)(g_EW + (size_t)i0 * D_DIM);
    const float4* r1 = (const float4*)(g_EW + (size_t)(KC0 + i1) * D_DIM);
    const float4* r2 = (const float4*)(g_EW + (size_t)(KC0 + KC1 + i2) * D_DIM);
    const float4* bb = (const float4*)bout;
    float4* o = (float4*)(out + (size_t)t * D_DIM);
    const int c = threadIdx.x;
    float4 a = r0[c], b = r1[c], cc = r2[c], d = bb[c];
    o[c] = make_float4(a.x + b.x + cc.x + d.x,
                       a.y + b.y + cc.y + d.y,
                       a.z + b.z + cc.z + d.z,
                       a.w + b.w + cc.w + d.w);
}

// ------------------- launch -------------------
extern "C" void kernel_launch(void* const* d_in, const int* in_sizes, int n_in,
                              void* d_out, int out_size) {
    const float* z     = (const float*)d_in[0];
    const float* W_in  = (const float*)d_in[1];
    const float* b_in  = (const float*)d_in[2];
    const float* W_out = (const float*)d_in[3];
    const float* b_out = (const float*)d_in[4];
    const float* e0    = (const float*)d_in[5];
    const float* e1    = (const float*)d_in[6];
    const float* e2    = (const float*)d_in[7];

    float* out      = (float*)d_out;
    float* out_idxf = out + (size_t)T_TOK * D_DIM;
    float* out_loss = out_idxf + 3 * T_TOK;

    // z_proj -> g_r
    k_gemm1<<<dim3(P_DIM / BN, T_TOK / BM), 256>>>(z, W_in, b_in);
    // codebook squared norms
    k_ssqE<<<2, 256>>>(e0, e1, e2);
    // EW table (independent of the VQ cascade)
    k_ew<<<(KC0 + KC1 + KC2) / 8, 256>>>(e0, e1, e2, W_out);

    // ---- level 0 ----
    k_ssr<<<T_TOK / 32, 32>>>();
    k_gemmS<KC0><<<dim3(KC0 / BN, T_TOK / BM), 256>>>(e0);
    k_pick<KC0, 0, 0><<<T_TOK / 8, 256>>>(e0, out_idxf);
    // ---- level 1 ----
    k_ssr<<<T_TOK / 32, 32>>>();
    k_gemmS<KC1><<<dim3(KC1 / BN, T_TOK / BM), 256>>>(e1);
    k_pick<KC1, 1, KC0><<<T_TOK / 8, 256>>>(e1, out_idxf);
    // ---- level 2 ----
    k_ssr<<<T_TOK / 32, 32>>>();
    k_gemmS<KC2><<<dim3(KC2 / BN, T_TOK / BM), 256>>>(e2);
    k_pick<KC2, 2, KC0 + KC1><<<T_TOK / 8, 256>>>(e2, out_idxf);

    k_lossred<<<1, 256>>>(out_loss);
    k_out<<<T_TOK, 352>>>(b_out, out);
}

// round 4
// speedup vs baseline: 1.0005x; 1.0005x over previous
#include <cuda_runtime.h>
#include <math_constants.h>

// Problem constants
#define T_TOK 32768     // B*N = 16*2048
#define D_DIM 1408
#define P_DIM 256
#define KC0 64
#define KC1 128
#define KC2 256

// GEMM tiling
#define BM 128
#define BN 64
#define BK 16

// ------------------- device scratch (static, no allocation) -------------------
static __device__ float  g_r[(size_t)T_TOK * P_DIM];        // residual (starts = z_proj), 33.5 MB
static __device__ float  g_S[(size_t)T_TOK * KC2];          // per-level scores, 33.5 MB
static __device__ float  g_ssr[T_TOK];                      // ||r||^2 per token (fp32, sequential)
static __device__ float  g_ssq[KC0 + KC1 + KC2];            // ||e_j||^2 (fp32, sequential)
static __device__ float  g_EW[(size_t)(KC0 + KC1 + KC2) * D_DIM];  // emb_cat @ W_out
static __device__ int    g_idx[3 * T_TOK];
static __device__ double g_losspart[3 * 4096];

// ------------------- GEMM1: z_proj = z @ W_in + b_in  (sequential-k fp32 FMA) ----
__global__ __launch_bounds__(256) void k_gemm1(const float* __restrict__ A,
                                               const float* __restrict__ W,
                                               const float* __restrict__ bias) {
    __shared__ float As[BK][BM + 4];
    __shared__ float Bs[BK][BN];
    const int tid = threadIdx.x;
    const int bm = blockIdx.y * BM;
    const int bn = blockIdx.x * BN;
    const int tr = (tid >> 4) << 3;
    const int tc = (tid & 15) << 2;

    float acc[8][4];
#pragma unroll
    for (int i = 0; i < 8; i++)
#pragma unroll
        for (int j = 0; j < 4; j++) acc[i][j] = 0.f;

    for (int k0 = 0; k0 < D_DIM; k0 += BK) {
#pragma unroll
        for (int i = 0; i < 2; i++) {
            int lid = tid * 2 + i;
            int ar = lid >> 2;
            int a4 = lid & 3;
            float4 v = *(const float4*)(A + (size_t)(bm + ar) * D_DIM + k0 + a4 * 4);
            As[a4 * 4 + 0][ar] = v.x;
            As[a4 * 4 + 1][ar] = v.y;
            As[a4 * 4 + 2][ar] = v.z;
            As[a4 * 4 + 3][ar] = v.w;
        }
        {
            int br = tid >> 4;
            int b4 = tid & 15;
            float4 v = *(const float4*)(W + (size_t)(k0 + br) * P_DIM + bn + b4 * 4);
            *(float4*)(&Bs[br][b4 * 4]) = v;
        }
        __syncthreads();
#pragma unroll
        for (int kk = 0; kk < BK; kk++) {   // strictly ascending k, single accumulator, FMA
            float4 b  = *(const float4*)(&Bs[kk][tc]);
            float4 a0 = *(const float4*)(&As[kk][tr]);
            float4 a1 = *(const float4*)(&As[kk][tr + 4]);
            float av[8] = {a0.x, a0.y, a0.z, a0.w, a1.x, a1.y, a1.z, a1.w};
            float bv[4] = {b.x, b.y, b.z, b.w};
#pragma unroll
            for (int i = 0; i < 8; i++)
#pragma unroll
                for (int j = 0; j < 4; j++) acc[i][j] = __fmaf_rn(av[i], bv[j], acc[i][j]);
        }
        __syncthreads();
    }
#pragma unroll
    for (int j = 0; j < 4; j++) {
        float bv = bias[bn + tc + j];
#pragma unroll
        for (int i = 0; i < 8; i++) acc[i][j] = __fadd_rn(acc[i][j], bv);
    }
#pragma unroll
    for (int i = 0; i < 8; i++) {
        float4 o = make_float4(acc[i][0], acc[i][1], acc[i][2], acc[i][3]);
        *(float4*)(g_r + (size_t)(bm + tr + i) * P_DIM + bn + tc) = o;
    }
}

// ------------------- ssq_j = sum(e_j * e_j)  (fp32: round products, sequential add) ----
__global__ __launch_bounds__(256) void k_ssqE(const float* __restrict__ e0,
                                              const float* __restrict__ e1,
                                              const float* __restrict__ e2) {
    int r = blockIdx.x * 256 + threadIdx.x;
    if (r >= KC0 + KC1 + KC2) return;
    const float* src = (r < KC0) ? (e0 + (size_t)r * P_DIM)
                     : (r < KC0 + KC1) ? (e1 + (size_t)(r - KC0) * P_DIM)
                                       : (e2 + (size_t)(r - KC0 - KC1) * P_DIM);
    float s = 0.f;
    for (int p = 0; p < P_DIM; p++) {
        float v = src[p];
        s = __fadd_rn(s, __fmul_rn(v, v));
    }
    g_ssq[r] = s;
}

// ------------------- ssr_t = sum(r_t * r_t)  (fp32: round products, sequential add) ----
__global__ __launch_bounds__(32) void k_ssr() {
    __shared__ float tile[32 * 257];
    const int tid = threadIdx.x;
    const size_t base = (size_t)blockIdx.x * 32;   // 1024 blocks x 32 tokens
    for (int i = tid; i < 32 * P_DIM; i += 32) {
        int row = i >> 8, col = i & 255;
        tile[row * 257 + col] = g_r[base * P_DIM + i];
    }
    __syncthreads();
    float s = 0.f;
    const float* rr = &tile[tid * 257];
    for (int p = 0; p < P_DIM; p++)
        s = __fadd_rn(s, __fmul_rn(rr[p], rr[p]));
    g_ssr[base + tid] = s;
}

// ------------------- S = r @ cb^T  (sequential-k fp32 FMA), K columns -------------------
template <int K>
__global__ __launch_bounds__(256) void k_gemmS(const float* __restrict__ cb) {
    __shared__ float As[BK][BM + 4];
    __shared__ float Bs[BK][BN + 4];
    const int tid = threadIdx.x;
    const int bm = blockIdx.y * BM;
    const int bn = blockIdx.x * BN;
    const int tr = (tid >> 4) << 3;
    const int tc = (tid & 15) << 2;

    float acc[8][4];
#pragma unroll
    for (int i = 0; i < 8; i++)
#pragma unroll
        for (int j = 0; j < 4; j++) acc[i][j] = 0.f;

    for (int k0 = 0; k0 < P_DIM; k0 += BK) {
#pragma unroll
        for (int i = 0; i < 2; i++) {
            int lid = tid * 2 + i;
            int ar = lid >> 2;
            int a4 = lid & 3;
            float4 v = *(const float4*)(g_r + (size_t)(bm + ar) * P_DIM + k0 + a4 * 4);
            As[a4 * 4 + 0][ar] = v.x;
            As[a4 * 4 + 1][ar] = v.y;
            As[a4 * 4 + 2][ar] = v.z;
            As[a4 * 4 + 3][ar] = v.w;
        }
        {
            int jr = tid >> 2;      // 0..63 codebook row within block
            int j4 = tid & 3;
            float4 v = *(const float4*)(cb + (size_t)(bn + jr) * P_DIM + k0 + j4 * 4);
            Bs[j4 * 4 + 0][jr] = v.x;
            Bs[j4 * 4 + 1][jr] = v.y;
            Bs[j4 * 4 + 2][jr] = v.z;
            Bs[j4 * 4 + 3][jr] = v.w;
        }
        __syncthreads();
#pragma unroll
        for (int kk = 0; kk < BK; kk++) {   // strictly ascending k, single accumulator, FMA
            float4 b  = *(const float4*)(&Bs[kk][tc]);
            float4 a0 = *(const float4*)(&As[kk][tr]);
            float4 a1 = *(const float4*)(&As[kk][tr + 4]);
            float av[8] = {a0.x, a0.y, a0.z, a0.w, a1.x, a1.y, a1.z, a1.w};
            float bv[4] = {b.x, b.y, b.z, b.w};
#pragma unroll
            for (int i = 0; i < 8; i++)
#pragma unroll
                for (int j = 0; j < 4; j++) acc[i][j] = __fmaf_rn(av[i], bv[j], acc[i][j]);
        }
        __syncthreads();
    }
#pragma unroll
    for (int i = 0; i < 8; i++) {
        float4 o = make_float4(acc[i][0], acc[i][1], acc[i][2], acc[i][3]);
        *(float4*)(g_S + (size_t)(bm + tr + i) * K + bn + tc) = o;
    }
}

// ------------------- per-level pick: d = (ssr - 2*S) + ssq ; argmin first-index ------
// Then residual update r -= e[idx] (fp32, identical op to reference) + fp64 loss partial.
template <int K, int LVL, int SSQ_OFF>
__global__ __launch_bounds__(256) void k_pick(const float* __restrict__ cb,
                                              float* __restrict__ out_idxf) {
    const int warp = threadIdx.x >> 5;
    const int lane = threadIdx.x & 31;
    const int t = blockIdx.x * 8 + warp;

    const float ssr = g_ssr[t];
    const float* Srow = g_S + (size_t)t * K;

    float best = CUDART_INF_F;
    int bi = 0x7fffffff;
#pragma unroll
    for (int kc = 0; kc < K / 32; kc++) {   // ascending j within lane
        int j = kc * 32 + lane;
        // reference rounding: (ssr - 2*S) then + ssq ; 2*S is exact
        float d = __fadd_rn(__fsub_rn(ssr, 2.0f * Srow[j]), g_ssq[SSQ_OFF + j]);
        if (d < best) { best = d; bi = j; }     // ties keep earlier (lower j)
    }
#pragma unroll
    for (int o = 16; o; o >>= 1) {              // cross-lane: first-min (lowest index on tie)
        float od = __shfl_xor_sync(0xffffffffu, best, o);
        int   oi = __shfl_xor_sync(0xffffffffu, bi, o);
        if (od < best || (od == best && oi < bi)) { best = od; bi = oi; }
    }
    const int idx = bi;

    // residual update + fp64 loss partial of new residual
    const float* er = cb + (size_t)idx * P_DIM;
    float* rrow = g_r + (size_t)t * P_DIM;
    double ls = 0.0;
#pragma unroll
    for (int k = 0; k < 8; k++) {
        int p = lane + 32 * k;
        float nv = __fsub_rn(rrow[p], er[p]);
        rrow[p] = nv;
        ls += (double)nv * (double)nv;
    }
#pragma unroll
    for (int o = 16; o; o >>= 1) ls += __shfl_xor_sync(0xffffffffu, ls, o);

    __shared__ double lsm[8];
    if (lane == 0) {
        g_idx[LVL * T_TOK + t] = idx;
        out_idxf[LVL * T_TOK + t] = (float)idx;
        lsm[warp] = ls;
    }
    __syncthreads();
    if (threadIdx.x == 0) {
        double tot = 0.0;
#pragma unroll
        for (int i = 0; i < 8; i++) tot += lsm[i];
        g_losspart[LVL * 4096 + blockIdx.x] = tot;
    }
}

// ------------------- loss reduce -------------------
__global__ __launch_bounds__(256) void k_lossred(float* __restrict__ out_loss) {
    __shared__ double sm[256];
    double s = 0.0;
    for (int i = threadIdx.x; i < 3 * 4096; i += 256) s += g_losspart[i];
    sm[threadIdx.x] = s;
    __syncthreads();
    for (int o = 128; o; o >>= 1) {
        if (threadIdx.x < o) sm[threadIdx.x] += sm[threadIdx.x + o];
        __syncthreads();
    }
    if (threadIdx.x == 0)
        *out_loss = (float)(sm[0] * (0.25 / (3.0 * (double)T_TOK * (double)P_DIM)));
}

// ------------------- EW = emb_cat @ W_out  [448,1408] -------------------
__global__ __launch_bounds__(256) void k_ew(const float* __restrict__ e0,
                                            const float* __restrict__ e1,
                                            const float* __restrict__ e2,
                                            const float* __restrict__ Wout) {
    __shared__ float a[8][P_DIM];
    const int rbase = blockIdx.x * 8;
    for (int i = threadIdx.x; i < 8 * P_DIM; i += 256) {
        int r = rbase + i / P_DIM;
        int p = i % P_DIM;
        const float* s = (r < KC0) ? (e0 + (size_t)r * P_DIM)
                       : (r < KC0 + KC1) ? (e1 + (size_t)(r - KC0) * P_DIM)
                                         : (e2 + (size_t)(r - KC0 - KC1) * P_DIM);
        a[i / P_DIM][p] = s[p];
    }
    __syncthreads();
    for (int c = threadIdx.x; c < D_DIM; c += 256) {
        float acc[8] = {0.f, 0.f, 0.f, 0.f, 0.f, 0.f, 0.f, 0.f};
        for (int p = 0; p < P_DIM; p++) {
            float w = Wout[(size_t)p * D_DIM + c];
#pragma unroll
            for (int r = 0; r < 8; r++) acc[r] = __fmaf_rn(a[r][p], w, acc[r]);
        }
#pragma unroll
        for (int r = 0; r < 8; r++) g_EW[(size_t)(rbase + r) * D_DIM + c] = acc[r];
    }
}

// ------------------- output gather: z_q_out = EW0[i0]+EW1[i1]+EW2[i2]+b_out ------------
__global__ __launch_bounds__(352) void k_out(const float* __restrict__ bout,
                                             float* __restrict__ out) {
    const int t = blockIdx.x;
    const int i0 = g_idx[t];
    const int i1 = g_idx[T_TOK + t];
    const int i2 = g_idx[2 * T_TOK + t];
    const float4* r0 = (const float4*)(g_EW + (size_t)i0 * D_DIM);
    const float4* r1 = (const float4*)(g_EW + (size_t)(KC0 + i1) * D_DIM);
    const float4* r2 = (const float4*)(g_EW + (size_t)(KC0 + KC1 + i2) * D_DIM);
    const float4* bb = (const float4*)bout;
    float4* o = (float4*)(out + (size_t)t * D_DIM);
    const int c = threadIdx.x;
    float4 a = r0[c], b = r1[c], cc = r2[c], d = bb[c];
    o[c] = make_float4(a.x + b.x + cc.x + d.x,
                       a.y + b.y + cc.y + d.y,
                       a.z + b.z + cc.z + d.z,
                       a.w + b.w + cc.w + d.w);
}

// ------------------- launch -------------------
extern "C" void kernel_launch(void* const* d_in, const int* in_sizes, int n_in,
                              void* d_out, int out_size) {
    const float* z     = (const float*)d_in[0];
    const float* W_in  = (const float*)d_in[1];
    const float* b_in  = (const float*)d_in[2];
    const float* W_out = (const float*)d_in[3];
    const float* b_out = (const float*)d_in[4];
    const float* e0    = (const float*)d_in[5];
    const float* e1    = (const float*)d_in[6];
    const float* e2    = (const float*)d_in[7];

    float* out      = (float*)d_out;
    float* out_idxf = out + (size_t)T_TOK * D_DIM;
    float* out_loss = out_idxf + 3 * T_TOK;

    // z_proj -> g_r
    k_gemm1<<<dim3(P_DIM / BN, T_TOK / BM), 256>>>(z, W_in, b_in);
    // codebook squared norms
    k_ssqE<<<2, 256>>>(e0, e1, e2);
    // EW table (independent of the VQ cascade)
    k_ew<<<(KC0 + KC1 + KC2) / 8, 256>>>(e0, e1, e2, W_out);

    // ---- level 0 ----
    k_ssr<<<T_TOK / 32, 32>>>();
    k_gemmS<KC0><<<dim3(KC0 / BN, T_TOK / BM), 256>>>(e0);
    k_pick<KC0, 0, 0><<<T_TOK / 8, 256>>>(e0, out_idxf);
    // ---- level 1 ----
    k_ssr<<<T_TOK / 32, 32>>>();
    k_gemmS<KC1><<<dim3(KC1 / BN, T_TOK / BM), 256>>>(e1);
    k_pick<KC1, 1, KC0><<<T_TOK / 8, 256>>>(e1, out_idxf);
    // ---- level 2 ----
    k_ssr<<<T_TOK / 32, 32>>>();
    k_gemmS<KC2><<<dim3(KC2 / BN, T_TOK / BM), 256>>>(e2);
    k_pick<KC2, 2, KC0 + KC1><<<T_TOK / 8, 256>>>(e2, out_idxf);

    k_lossred<<<1, 256>>>(out_loss);
    k_out<<<T_TOK, 352>>>(b_out, out);
}

// round 7
// speedup vs baseline: 1.0922x; 1.0916x over previous
#include <cuda_runtime.h>
#include <cuda_bf16.h>
#include <math_constants.h>
#include <cstdint>

#define T_TOK 32768
#define D_DIM 1408
#define P_DIM 256
#define KC0 64
#define KC1 128
#define KC2 256
#define TAU 3e-3f

// ------------------- device scratch -------------------
static __device__ float  g_r[(size_t)T_TOK * P_DIM];      // approx zproj -> residual
static __device__ float  g_S[(size_t)T_TOK * KC2];        // scores; later reused as exact-zproj store
static __device__ float  g_ssq[KC0 + KC1 + KC2];
static __device__ float  g_EW[(size_t)(KC0 + KC1 + KC2) * D_DIM];
static __device__ int    g_idx[3 * T_TOK];
static __device__ float  g_losstok[T_TOK];
static __device__ int    g_flagged[T_TOK];
static __device__ int    g_flagcnt[1];
static __device__ int    g_flaglist[T_TOK];
static __device__ __nv_bfloat16 g_WhiT[(size_t)P_DIM * D_DIM];   // W_in^T hi [256][1408]
static __device__ __nv_bfloat16 g_WloT[(size_t)P_DIM * D_DIM];   // W_in^T lo
static __device__ __nv_bfloat16 g_cbh[(KC0 + KC1 + KC2) * P_DIM]; // codebooks hi [448][256]
static __device__ __nv_bfloat16 g_cbl[(KC0 + KC1 + KC2) * P_DIM]; // codebooks lo

// ------------------- helpers -------------------
__device__ __forceinline__ uint32_t smem_u32(const void* p) {
    uint32_t a;
    asm("{ .reg .u64 t; cvta.to.shared.u64 t, %1; cvt.u32.u64 %0, t; }" : "=r"(a) : "l"(p));
    return a;
}
__device__ __forceinline__ void ldm4(uint32_t r[4], uint32_t a) {
    asm volatile("ldmatrix.sync.aligned.m8n8.x4.shared.b16 {%0,%1,%2,%3}, [%4];"
                 : "=r"(r[0]), "=r"(r[1]), "=r"(r[2]), "=r"(r[3]) : "r"(a));
}
__device__ __forceinline__ void mma_bf16(float c[4], const uint32_t a[4], const uint32_t b[2]) {
    asm volatile("mma.sync.aligned.m16n8k16.row.col.f32.bf16.bf16.f32 "
                 "{%0,%1,%2,%3}, {%4,%5,%6,%7}, {%8,%9}, {%0,%1,%2,%3};"
                 : "+f"(c[0]), "+f"(c[1]), "+f"(c[2]), "+f"(c[3])
                 : "r"(a[0]), "r"(a[1]), "r"(a[2]), "r"(a[3]), "r"(b[0]), "r"(b[1]));
}
__device__ __forceinline__ void split_bf16(float v, __nv_bfloat16& h, __nv_bfloat16& l) {
    h = __float2bfloat16_rn(v);
    l = __float2bfloat16_rn(v - __bfloat162float(h));
}

// ------------------- zero flags -------------------
__global__ __launch_bounds__(256) void k_zero() {
    int i = blockIdx.x * 256 + threadIdx.x;
    for (; i < T_TOK; i += gridDim.x * 256) g_flagged[i] = 0;
    if (blockIdx.x == 0 && threadIdx.x == 0) g_flagcnt[0] = 0;
}

// ------------------- W_in split + transpose -> WT hi/lo [256][1408] bf16 -------------
__global__ __launch_bounds__(256) void k_wprep(const float* __restrict__ Win) {
    __shared__ float tile[32][33];
    const int r0 = blockIdx.x * 32, c0 = blockIdx.y * 32;
    const int tx = threadIdx.x & 31, ty = threadIdx.x >> 5;
    for (int rr = ty; rr < 32; rr += 8)
        tile[rr][tx] = Win[(size_t)(r0 + rr) * P_DIM + c0 + tx];
    __syncthreads();
    for (int rr = ty; rr < 32; rr += 8) {
        __nv_bfloat16 h, l;
        split_bf16(tile[tx][rr], h, l);
        g_WhiT[(size_t)(c0 + rr) * D_DIM + r0 + tx] = h;
        g_WloT[(size_t)(c0 + rr) * D_DIM + r0 + tx] = l;
    }
}

// ------------------- codebook split -> g_cbh/g_cbl [448][256] -------------------
__global__ __launch_bounds__(256) void k_cbprep(const float* __restrict__ e0,
                                                const float* __restrict__ e1,
                                                const float* __restrict__ e2) {
    const int row = blockIdx.x;          // 0..447
    const float* src = (row < KC0) ? (e0 + (size_t)row * P_DIM)
                     : (row < KC0 + KC1) ? (e1 + (size_t)(row - KC0) * P_DIM)
                                         : (e2 + (size_t)(row - KC0 - KC1) * P_DIM);
    const int p = threadIdx.x;
    __nv_bfloat16 h, l;
    split_bf16(src[p], h, l);
    g_cbh[row * P_DIM + p] = h;
    g_cbl[row * P_DIM + p] = l;
}

// ------------------- GEMM1 via mma.sync bf16x3: g_r ~= z @ W_in + b_in ---------------
// CTA 128(M) x 128(N of P=256); warps 2x4 (64x32 tiles). K chunks of 32 (44 iters).
__global__ __launch_bounds__(256, 1) void k_gemm1_mma(const float* __restrict__ z,
                                                      const float* __restrict__ bin) {
    __shared__ __nv_bfloat16 Ah[128][40], Al[128][40], Bh[128][40], Bl[128][40];
    const int tid = threadIdx.x, wid = tid >> 5, lane = tid & 31;
    const int warp_m = wid >> 2, warp_n = wid & 3;
    const size_t bm = (size_t)blockIdx.y * 128;
    const int bnG = blockIdx.x * 128;
    const uint32_t sAh = smem_u32(Ah), sAl = smem_u32(Al);
    const uint32_t sBh = smem_u32(Bh), sBl = smem_u32(Bl);
    const int g = lane >> 3, lr = lane & 7;

    float acc[4][4][4];
#pragma unroll
    for (int mt = 0; mt < 4; mt++)
#pragma unroll
        for (int nt = 0; nt < 4; nt++)
#pragma unroll
            for (int q = 0; q < 4; q++) acc[mt][nt][q] = 0.f;

    for (int kc = 0; kc < D_DIM / 32; kc++) {
        const int k0 = kc * 32;
        // A: z[bm..+128][k0..+32] fp32 -> hi/lo bf16
#pragma unroll
        for (int q = 0; q < 4; q++) {
            int i = tid + q * 256;          // 1024 float4
            int r = i >> 3, c4 = i & 7;
            float4 v = *(const float4*)(z + (bm + r) * D_DIM + k0 + c4 * 4);
            __nv_bfloat16 h0, l0, h1, l1, h2, l2, h3, l3;
            split_bf16(v.x, h0, l0); split_bf16(v.y, h1, l1);
            split_bf16(v.z, h2, l2); split_bf16(v.w, h3, l3);
            __nv_bfloat162 ph0 = __halves2bfloat162(h0, h1), ph1 = __halves2bfloat162(h2, h3);
            __nv_bfloat162 pl0 = __halves2bfloat162(l0, l1), pl1 = __halves2bfloat162(l2, l3);
            *(uint2*)&Ah[r][c4 * 4] = make_uint2(*(uint32_t*)&ph0, *(uint32_t*)&ph1);
            *(uint2*)&Al[r][c4 * 4] = make_uint2(*(uint32_t*)&pl0, *(uint32_t*)&pl1);
        }
        // B: WT[bnG+n][k0..+32] bf16 hi/lo
#pragma unroll
        for (int q = 0; q < 2; q++) {
            int i = tid + q * 256;          // 512 x 16B
            int n = i >> 2, c = i & 3;
            *(uint4*)&Bh[n][c * 8] = *(const uint4*)(g_WhiT + (size_t)(bnG + n) * D_DIM + k0 + c * 8);
            *(uint4*)&Bl[n][c * 8] = *(const uint4*)(g_WloT + (size_t)(bnG + n) * D_DIM + k0 + c * 8);
        }
        __syncthreads();
#pragma unroll
        for (int ks = 0; ks < 2; ks++) {
            const int kk = ks * 16;
            uint32_t bhf[4][2], blf[4][2];
#pragma unroll
            for (int p = 0; p < 2; p++) {   // n-tile pairs
                const int n0 = warp_n * 32 + p * 16;
                uint32_t off = (uint32_t)((n0 + ((g >> 1) << 3) + lr) * 40 + kk + ((g & 1) << 3)) * 2;
                uint32_t t[4];
                ldm4(t, sBh + off);
                bhf[p * 2][0] = t[0]; bhf[p * 2][1] = t[1];
                bhf[p * 2 + 1][0] = t[2]; bhf[p * 2 + 1][1] = t[3];
                ldm4(t, sBl + off);
                blf[p * 2][0] = t[0]; blf[p * 2][1] = t[1];
                blf[p * 2 + 1][0] = t[2]; blf[p * 2 + 1][1] = t[3];
            }
#pragma unroll
            for (int mt = 0; mt < 4; mt++) {
                const int m0 = warp_m * 64 + mt * 16;
                uint32_t aoff = (uint32_t)((m0 + ((g & 1) << 3) + lr) * 40 + kk + ((g >> 1) << 3)) * 2;
                uint32_t ah[4], al[4];
                ldm4(ah, sAh + aoff);
                ldm4(al, sAl + aoff);
#pragma unroll
                for (int nt = 0; nt < 4; nt++) {
                    mma_bf16(acc[mt][nt], ah, bhf[nt]);
                    mma_bf16(acc[mt][nt], ah, blf[nt]);
                    mma_bf16(acc[mt][nt], al, bhf[nt]);
                }
            }
        }
        __syncthreads();
    }
    // epilogue + bias
#pragma unroll
    for (int mt = 0; mt < 4; mt++) {
        const size_t row = bm + warp_m * 64 + mt * 16 + (lane >> 2);
#pragma unroll
        for (int nt = 0; nt < 4; nt++) {
            const int col = bnG + warp_n * 32 + nt * 8 + ((lane & 3) << 1);
            float b0 = bin[col], b1 = bin[col + 1];
            *(float2*)(g_r + row * P_DIM + col) =
                make_float2(acc[mt][nt][0] + b0, acc[mt][nt][1] + b1);
            *(float2*)(g_r + (row + 8) * P_DIM + col) =
                make_float2(acc[mt][nt][2] + b0, acc[mt][nt][3] + b1);
        }
    }
}

// ------------------- GEMMS via mma.sync bf16x3: S ~= r @ cb^T ------------------------
// CTA 128(M) x 64(N); warps 4x2 (32x32 tiles). K = 256, chunks of 32 (8 iters).
template <int KN>
__global__ __launch_bounds__(256, 1) void k_gemmS_mma(int cboff) {
    __shared__ __nv_bfloat16 Ah[128][40], Al[128][40], Bh[64][40], Bl[64][40];
    const int tid = threadIdx.x, wid = tid >> 5, lane = tid & 31;
    const int warp_m = wid >> 1, warp_n = wid & 1;
    const size_t bm = (size_t)blockIdx.y * 128;
    const int bn = blockIdx.x * 64;
    const uint32_t sAh = smem_u32(Ah), sAl = smem_u32(Al);
    const uint32_t sBh = smem_u32(Bh), sBl = smem_u32(Bl);
    const int g = lane >> 3, lr = lane & 7;

    float acc[2][4][4];
#pragma unroll
    for (int mt = 0; mt < 2; mt++)
#pragma unroll
        for (int nt = 0; nt < 4; nt++)
#pragma unroll
            for (int q = 0; q < 4; q++) acc[mt][nt][q] = 0.f;

    for (int kc = 0; kc < P_DIM / 32; kc++) {
        const int k0 = kc * 32;
#pragma unroll
        for (int q = 0; q < 4; q++) {
            int i = tid + q * 256;
            int r = i >> 3, c4 = i & 7;
            float4 v = *(const float4*)(g_r + (bm + r) * P_DIM + k0 + c4 * 4);
            __nv_bfloat16 h0, l0, h1, l1, h2, l2, h3, l3;
            split_bf16(v.x, h0, l0); split_bf16(v.y, h1, l1);
            split_bf16(v.z, h2, l2); split_bf16(v.w, h3, l3);
            __nv_bfloat162 ph0 = __halves2bfloat162(h0, h1), ph1 = __halves2bfloat162(h2, h3);
            __nv_bfloat162 pl0 = __halves2bfloat162(l0, l1), pl1 = __halves2bfloat162(l2, l3);
            *(uint2*)&Ah[r][c4 * 4] = make_uint2(*(uint32_t*)&ph0, *(uint32_t*)&ph1);
            *(uint2*)&Al[r][c4 * 4] = make_uint2(*(uint32_t*)&pl0, *(uint32_t*)&pl1);
        }
        {
            int n = tid >> 2, c = tid & 3;   // 256 threads cover 64 rows x 4 chunks
            *(uint4*)&Bh[n][c * 8] = *(const uint4*)(g_cbh + (size_t)(cboff + bn + n) * P_DIM + k0 + c * 8);
            *(uint4*)&Bl[n][c * 8] = *(const uint4*)(g_cbl + (size_t)(cboff + bn + n) * P_DIM + k0 + c * 8);
        }
        __syncthreads();
#pragma unroll
        for (int ks = 0; ks < 2; ks++) {
            const int kk = ks * 16;
            uint32_t bhf[4][2], blf[4][2];
#pragma unroll
            for (int p = 0; p < 2; p++) {
                const int n0 = warp_n * 32 + p * 16;
                uint32_t off = (uint32_t)((n0 + ((g >> 1) << 3) + lr) * 40 + kk + ((g & 1) << 3)) * 2;
                uint32_t t[4];
                ldm4(t, sBh + off);
                bhf[p * 2][0] = t[0]; bhf[p * 2][1] = t[1];
                bhf[p * 2 + 1][0] = t[2]; bhf[p * 2 + 1][1] = t[3];
                ldm4(t, sBl + off);
                blf[p * 2][0] = t[0]; blf[p * 2][1] = t[1];
                blf[p * 2 + 1][0] = t[2]; blf[p * 2 + 1][1] = t[3];
            }
#pragma unroll
            for (int mt = 0; mt < 2; mt++) {
                const int m0 = warp_m * 32 + mt * 16;
                uint32_t aoff = (uint32_t)((m0 + ((g & 1) << 3) + lr) * 40 + kk + ((g >> 1) << 3)) * 2;
                uint32_t ah[4], al[4];
                ldm4(ah, sAh + aoff);
                ldm4(al, sAl + aoff);
#pragma unroll
                for (int nt = 0; nt < 4; nt++) {
                    mma_bf16(acc[mt][nt], ah, bhf[nt]);
                    mma_bf16(acc[mt][nt], ah, blf[nt]);
                    mma_bf16(acc[mt][nt], al, bhf[nt]);
                }
            }
        }
        __syncthreads();
    }
#pragma unroll
    for (int mt = 0; mt < 2; mt++) {
        const size_t row = bm + warp_m * 32 + mt * 16 + (lane >> 2);
#pragma unroll
        for (int nt = 0; nt < 4; nt++) {
            const int col = bn + warp_n * 32 + nt * 8 + ((lane & 3) << 1);
            *(float2*)(g_S + row * KN + col) = make_float2(acc[mt][nt][0], acc[mt][nt][1]);
            *(float2*)(g_S + (row + 8) * KN + col) = make_float2(acc[mt][nt][2], acc[mt][nt][3]);
        }
    }
}

// ------------------- ssq (exact fp32 sequential) -------------------
__global__ __launch_bounds__(256) void k_ssqE(const float* __restrict__ e0,
                                              const float* __restrict__ e1,
                                              const float* __restrict__ e2) {
    int r = blockIdx.x * 256 + threadIdx.x;
    if (r >= KC0 + KC1 + KC2) return;
    const float* src = (r < KC0) ? (e0 + (size_t)r * P_DIM)
                     : (r < KC0 + KC1) ? (e1 + (size_t)(r - KC0) * P_DIM)
                                       : (e2 + (size_t)(r - KC0 - KC1) * P_DIM);
    float s = 0.f;
    for (int p = 0; p < P_DIM; p++) s = __fadd_rn(s, __fmul_rn(src[p], src[p]));
    g_ssq[r] = s;
}

// ------------------- pick (approx) + gap flag + residual + per-token loss ------------
template <int K, int LVL, int SSQ_OFF>
__global__ __launch_bounds__(256) void k_pick(const float* __restrict__ cb,
                                              float* __restrict__ out_idxf) {
    const int warp = threadIdx.x >> 5, lane = threadIdx.x & 31;
    const int t = blockIdx.x * 8 + warp;
    const float* Srow = g_S + (size_t)t * K;

    float m1 = CUDART_INF_F, m2 = CUDART_INF_F;
    int i1 = 0x7fffffff;
#pragma unroll
    for (int kc = 0; kc < K / 32; kc++) {
        int j = kc * 32 + lane;
        float d = __fsub_rn(g_ssq[SSQ_OFF + j], 2.0f * Srow[j]);
        if (d < m1) { m2 = m1; m1 = d; i1 = j; }
        else m2 = fminf(m2, d);
    }
#pragma unroll
    for (int o = 16; o; o >>= 1) {
        float om1 = __shfl_xor_sync(0xffffffffu, m1, o);
        int   oi1 = __shfl_xor_sync(0xffffffffu, i1, o);
        float om2 = __shfl_xor_sync(0xffffffffu, m2, o);
        if (om1 < m1 || (om1 == m1 && oi1 < i1)) { m2 = fminf(m1, om2); m1 = om1; i1 = oi1; }
        else m2 = fminf(m2, om1);
    }
    const int idx = i1;

    const float* er = cb + (size_t)idx * P_DIM;
    float* rrow = g_r + (size_t)t * P_DIM;
    double ls = 0.0;
#pragma unroll
    for (int k = 0; k < 8; k++) {
        int p = lane + 32 * k;
        float nv = __fsub_rn(rrow[p], er[p]);
        rrow[p] = nv;
        ls += (double)nv * (double)nv;
    }
#pragma unroll
    for (int o = 16; o; o >>= 1) ls += __shfl_xor_sync(0xffffffffu, ls, o);

    if (lane == 0) {
        g_idx[LVL * T_TOK + t] = idx;
        out_idxf[LVL * T_TOK + t] = (float)idx;
        if (m2 - m1 < TAU) g_flagged[t] = 1;
        if (LVL == 0) g_losstok[t] = (float)ls;
        else g_losstok[t] += (float)ls;
    }
}

// ------------------- compact flag list -------------------
__global__ __launch_bounds__(256) void k_compact() {
    int i = blockIdx.x * 256 + threadIdx.x;
    for (; i < T_TOK; i += gridDim.x * 256)
        if (g_flagged[i]) g_flaglist[atomicAdd(&g_flagcnt[0], 1)] = i;
}

// ------------------- fixup A: exact zproj for flagged tokens -------------------------
__global__ __launch_bounds__(256, 1) void k_fixA(const float* __restrict__ z,
                                                 const float* __restrict__ Win,
                                                 const float* __restrict__ bin) {
    extern __shared__ char sm[];
    float* zsm = (float*)sm;                 // [32][68]
    float* Wsm = (float*)(sm + 32 * 68 * 4); // [64][256]
    __shared__ int tl[32];
    const int tid = threadIdx.x;
    const int cnt = g_flagcnt[0];
    if (cnt == 0) return;

    for (int base = blockIdx.x * 32; base < cnt; base += gridDim.x * 32) {
        if (tid < 32) tl[tid] = g_flaglist[min(base + tid, cnt - 1)];
        __syncthreads();
        const int tg = tid >> 5, cg = tid & 31;     // 8 token-groups x 32 col-threads
        float acc[4][8];
#pragma unroll
        for (int a = 0; a < 4; a++)
#pragma unroll
            for (int b = 0; b < 8; b++) acc[a][b] = 0.f;

        for (int kc = 0; kc < D_DIM / 64; kc++) {
#pragma unroll
            for (int q = 0; q < 2; q++) {
                int i = tid + q * 256;
                int s = i >> 4, c4 = i & 15;
                *(float4*)(zsm + s * 68 + c4 * 4) =
                    *(const float4*)(z + (size_t)tl[s] * D_DIM + kc * 64 + c4 * 4);
            }
#pragma unroll
            for (int q = 0; q < 16; q++) {
                int i = tid + q * 256;
                int k = i >> 6, c4 = i & 63;
                *(float4*)(Wsm + k * 256 + c4 * 4) =
                    *(const float4*)(Win + (size_t)(kc * 64 + k) * P_DIM + c4 * 4);
            }
            __syncthreads();
            for (int k = 0; k < 64; k++) {
                float4 w0 = *(const float4*)(Wsm + k * 256 + cg * 8);
                float4 w1 = *(const float4*)(Wsm + k * 256 + cg * 8 + 4);
                float wv[8] = {w0.x, w0.y, w0.z, w0.w, w1.x, w1.y, w1.z, w1.w};
#pragma unroll
                for (int a = 0; a < 4; a++) {
                    float zv = zsm[(tg * 4 + a) * 68 + k];
#pragma unroll
                    for (int b = 0; b < 8; b++)
                        acc[a][b] = __fmaf_rn(zv, wv[b], acc[a][b]);
                }
            }
            __syncthreads();
        }
#pragma unroll
        for (int a = 0; a < 4; a++) {
            int s = tg * 4 + a;
            if (base + s < cnt) {
                float* dst = g_S + (size_t)tl[s] * P_DIM;   // reuse g_S as exact zproj
#pragma unroll
                for (int b = 0; b < 8; b++)
                    dst[cg * 8 + b] = __fadd_rn(acc[a][b], bin[cg * 8 + b]);
            }
        }
        __syncthreads();
    }
}

// ------------------- fixup B: exact cascade (Round-3 arithmetic) ----------------------
__global__ __launch_bounds__(256, 1) void k_fixB(const float* __restrict__ e0,
                                                 const float* __restrict__ e1,
                                                 const float* __restrict__ e2,
                                                 float* __restrict__ out_idxf) {
    extern __shared__ char sm[];
    float* r8  = (float*)sm;                                  // [8][257]
    float* cbs = (float*)(sm + 8 * 257 * 4);                  // [128][257]
    float* Ssm = (float*)(sm + 8 * 257 * 4 + 128 * 257 * 4);  // [8][256]
    __shared__ float ssr8[8];
    __shared__ int tl[8];
    const int tid = threadIdx.x, warp = tid >> 5, lane = tid & 31;
    const int cnt = g_flagcnt[0];
    if (cnt == 0) return;
    const float* cbl_[3] = {e0, e1, e2};
    const int Kl[3] = {KC0, KC1, KC2};
    const int offl[3] = {0, KC0, KC0 + KC1};

    for (int base = blockIdx.x * 8; base < cnt; base += gridDim.x * 8) {
        if (tid < 8) tl[tid] = g_flaglist[min(base + tid, cnt - 1)];
        __syncthreads();
        for (int i = tid; i < 8 * 256; i += 256)
            r8[(i >> 8) * 257 + (i & 255)] = g_S[(size_t)tl[i >> 8] * P_DIM + (i & 255)];
        __syncthreads();
        if (tid < 8) {
            float s = 0.f;
            for (int p = 0; p < P_DIM; p++)
                s = __fadd_rn(s, __fmul_rn(r8[tid * 257 + p], r8[tid * 257 + p]));
            ssr8[tid] = s;
        }
        __syncthreads();

        int myidx[3];
        double lsd = 0.0;
        for (int lvl = 0; lvl < 3; lvl++) {
            const int K = Kl[lvl];
            const float* cb = cbl_[lvl];
            for (int ch = 0; ch < (K + 127) / 128; ch++) {
                const int rows = min(128, K - ch * 128);
                for (int i = tid; i < rows * 256; i += 256)
                    cbs[(i >> 8) * 257 + (i & 255)] =
                        cb[(size_t)(ch * 128 + (i >> 8)) * P_DIM + (i & 255)];
                __syncthreads();
                for (int m = 0; m < rows / 32; m++) {
                    int jl = m * 32 + lane;
                    float a = 0.f;
                    for (int p = 0; p < P_DIM; p++)
                        a = __fmaf_rn(r8[warp * 257 + p], cbs[jl * 257 + p], a);
                    Ssm[warp * 256 + ch * 128 + jl] = a;
                }
                __syncthreads();
            }
            const float ssr = ssr8[warp];
            float best = CUDART_INF_F;
            int bi = 0x7fffffff;
            for (int kc = 0; kc < K / 32; kc++) {
                int j = kc * 32 + lane;
                float d = __fadd_rn(__fsub_rn(ssr, 2.0f * Ssm[warp * 256 + j]),
                                    g_ssq[offl[lvl] + j]);
                if (d < best) { best = d; bi = j; }
            }
#pragma unroll
            for (int o = 16; o; o >>= 1) {
                float od = __shfl_xor_sync(0xffffffffu, best, o);
                int   oi = __shfl_xor_sync(0xffffffffu, bi, o);
                if (od < best || (od == best && oi < bi)) { best = od; bi = oi; }
            }
            myidx[lvl] = bi;
            const float* er = cb + (size_t)bi * P_DIM;
            double lp = 0.0;
#pragma unroll
            for (int k = 0; k < 8; k++) {
                int p = lane + 32 * k;
                float nv = __fsub_rn(r8[warp * 257 + p], er[p]);
                r8[warp * 257 + p] = nv;
                lp += (double)nv * (double)nv;
            }
#pragma unroll
            for (int o = 16; o; o >>= 1) lp += __shfl_xor_sync(0xffffffffu, lp, o);
            lsd += lp;
            __syncwarp();
            if (lane == 0 && lvl < 2) {
                float s = 0.f;
                for (int p = 0; p < P_DIM; p++)
                    s = __fadd_rn(s, __fmul_rn(r8[warp * 257 + p], r8[warp * 257 + p]));
                ssr8[warp] = s;
            }
            __syncthreads();
        }
        if (lane == 0 && base + warp < cnt) {
            int t = tl[warp];
            g_idx[t] = myidx[0]; g_idx[T_TOK + t] = myidx[1]; g_idx[2 * T_TOK + t] = myidx[2];
            out_idxf[t] = (float)myidx[0];
            out_idxf[T_TOK + t] = (float)myidx[1];
            out_idxf[2 * T_TOK + t] = (float)myidx[2];
            g_losstok[t] = (float)lsd;
        }
        __syncthreads();
    }
}

// ------------------- loss reduce -------------------
__global__ __launch_bounds__(256) void k_lossred(float* __restrict__ out_loss) {
    __shared__ double smm[256];
    double s = 0.0;
    for (int i = threadIdx.x; i < T_TOK; i += 256) s += (double)g_losstok[i];
    smm[threadIdx.x] = s;
    __syncthreads();
    for (int o = 128; o; o >>= 1) {
        if (threadIdx.x < o) smm[threadIdx.x] += smm[threadIdx.x + o];
        __syncthreads();
    }
    if (threadIdx.x == 0)
        *out_loss = (float)(smm[0] * (0.25 / (3.0 * (double)T_TOK * (double)P_DIM)));
}

// ------------------- EW = emb_cat @ W_out -------------------
__global__ __launch_bounds__(256) void k_ew(const float* __restrict__ e0,
                                            const float* __restrict__ e1,
                                            const float* __restrict__ e2,
                                            const float* __restrict__ Wout) {
    __shared__ float a[8][P_DIM];
    const int rbase = blockIdx.x * 8;
    for (int i = threadIdx.x; i < 8 * P_DIM; i += 256) {
        int r = rbase + i / P_DIM, p = i % P_DIM;
        const float* s = (r < KC0) ? (e0 + (size_t)r * P_DIM)
                       : (r < KC0 + KC1) ? (e1 + (size_t)(r - KC0) * P_DIM)
                                         : (e2 + (size_t)(r - KC0 - KC1) * P_DIM);
        a[i / P_DIM][p] = s[p];
    }
    __syncthreads();
    for (int c = threadIdx.x; c < D_DIM; c += 256) {
        float acc[8] = {0.f, 0.f, 0.f, 0.f, 0.f, 0.f, 0.f, 0.f};
        for (int p = 0; p < P_DIM; p++) {
            float w = Wout[(size_t)p * D_DIM + c];
#pragma unroll
            for (int r = 0; r < 8; r++) acc[r] = __fmaf_rn(a[r][p], w, acc[r]);
        }
#pragma unroll
        for (int r = 0; r < 8; r++) g_EW[(size_t)(rbase + r) * D_DIM + c] = acc[r];
    }
}

// ------------------- output gather -------------------
__global__ __launch_bounds__(352) void k_out(const float* __restrict__ bout,
                                             float* __restrict__ out) {
    const int t = blockIdx.x;
    const int i0 = g_idx[t], i1 = g_idx[T_TOK + t], i2 = g_idx[2 * T_TOK + t];
    const float4* r0 = (const float4*)(g_EW + (size_t)i0 * D_DIM);
    const float4* r1 = (const float4*)(g_EW + (size_t)(KC0 + i1) * D_DIM);
    const float4* r2 = (const float4*)(g_EW + (size_t)(KC0 + KC1 + i2) * D_DIM);
    const float4* bb = (const float4*)bout;
    float4* o = (float4*)(out + (size_t)t * D_DIM);
    const int c = threadIdx.x;
    float4 a = r0[c], b = r1[c], cc = r2[c], d = bb[c];
    o[c] = make_float4(a.x + b.x + cc.x + d.x, a.y + b.y + cc.y + d.y,
                       a.z + b.z + cc.z + d.z, a.w + b.w + cc.w + d.w);
}

// ------------------- launch -------------------
extern "C" void kernel_launch(void* const* d_in, const int* in_sizes, int n_in,
                              void* d_out, int out_size) {
    const float* z     = (const float*)d_in[0];
    const float* W_in  = (const float*)d_in[1];
    const float* b_in  = (const float*)d_in[2];
    const float* W_out = (const float*)d_in[3];
    const float* b_out = (const float*)d_in[4];
    const float* e0    = (const float*)d_in[5];
    const float* e1    = (const float*)d_in[6];
    const float* e2    = (const float*)d_in[7];

    float* out      = (float*)d_out;
    float* out_idxf = out + (size_t)T_TOK * D_DIM;
    float* out_loss = out_idxf + 3 * T_TOK;

    cudaFuncSetAttribute(k_fixA, cudaFuncAttributeMaxDynamicSharedMemorySize,
                         32 * 68 * 4 + 64 * 256 * 4);
    cudaFuncSetAttribute(k_fixB, cudaFuncAttributeMaxDynamicSharedMemorySize,
                         8 * 257 * 4 + 128 * 257 * 4 + 8 * 256 * 4);

    k_zero<<<128, 256>>>();
    k_wprep<<<dim3(D_DIM / 32, P_DIM / 32), 256>>>(W_in);
    k_cbprep<<<KC0 + KC1 + KC2, 256>>>(e0, e1, e2);
    k_ssqE<<<2, 256>>>(e0, e1, e2);
    k_ew<<<(KC0 + KC1 + KC2) / 8, 256>>>(e0, e1, e2, W_out);

    k_gemm1_mma<<<dim3(2, T_TOK / 128), 256>>>(z, b_in);

    k_gemmS_mma<KC0><<<dim3(KC0 / 64, T_TOK / 128), 256>>>(0);
    k_pick<KC0, 0, 0><<<T_TOK / 8, 256>>>(e0, out_idxf);
    k_gemmS_mma<KC1><<<dim3(KC1 / 64, T_TOK / 128), 256>>>(KC0);
    k_pick<KC1, 1, KC0><<<T_TOK / 8, 256>>>(e1, out_idxf);
    k_gemmS_mma<KC2><<<dim3(KC2 / 64, T_TOK / 128), 256>>>(KC0 + KC1);
    k_pick<KC2, 2, KC0 + KC1><<<T_TOK / 8, 256>>>(e2, out_idxf);

    k_compact<<<64, 256>>>();
    k_fixA<<<256, 256, 32 * 68 * 4 + 64 * 256 * 4>>>(z, W_in, b_in);
    k_fixB<<<512, 256, 8 * 257 * 4 + 128 * 257 * 4 + 8 * 256 * 4>>>(e0, e1, e2, out_idxf);

    k_lossred<<<1, 256>>>(out_loss);
    k_out<<<T_TOK, 352>>>(b_out, out);
}

// round 8
// speedup vs baseline: 1.1501x; 1.0531x over previous
#include <cuda_runtime.h>
#include <cuda_bf16.h>
#include <math_constants.h>
#include <cstdint>

#define T_TOK 32768
#define D_DIM 1408
#define P_DIM 256
#define KC0 64
#define KC1 128
#define KC2 256
#define KT  448
#define TAU 3e-3f

// ------------------- device scratch -------------------
static __device__ float  g_r[(size_t)T_TOK * P_DIM];      // zproj (approx); fast path never mutates
static __device__ float  g_S[(size_t)T_TOK * KT];         // scores [T][448]; later reused as exact-zproj store
static __device__ float  g_ssq[KT];
static __device__ float  g_ssr[T_TOK];
static __device__ float  g_G01[KC0 * KC1];
static __device__ float  g_G02[KC0 * KC2];
static __device__ float  g_G12[KC1 * KC2];
static __device__ float  g_EW[(size_t)KT * D_DIM];
static __device__ int    g_idx[3 * T_TOK];
static __device__ float  g_losstok[T_TOK];
static __device__ int    g_flagged[T_TOK];
static __device__ int    g_flagcnt[1];
static __device__ int    g_flaglist[T_TOK];
static __device__ __nv_bfloat16 g_WhiT[(size_t)P_DIM * D_DIM];
static __device__ __nv_bfloat16 g_WloT[(size_t)P_DIM * D_DIM];
static __device__ __nv_bfloat16 g_cbh[KT * P_DIM];
static __device__ __nv_bfloat16 g_cbl[KT * P_DIM];

// ------------------- helpers -------------------
__device__ __forceinline__ uint32_t smem_u32(const void* p) {
    uint32_t a;
    asm("{ .reg .u64 t; cvta.to.shared.u64 t, %1; cvt.u32.u64 %0, t; }" : "=r"(a) : "l"(p));
    return a;
}
__device__ __forceinline__ void ldm4(uint32_t r[4], uint32_t a) {
    asm volatile("ldmatrix.sync.aligned.m8n8.x4.shared.b16 {%0,%1,%2,%3}, [%4];"
                 : "=r"(r[0]), "=r"(r[1]), "=r"(r[2]), "=r"(r[3]) : "r"(a));
}
__device__ __forceinline__ void mma_bf16(float c[4], const uint32_t a[4], const uint32_t b[2]) {
    asm volatile("mma.sync.aligned.m16n8k16.row.col.f32.bf16.bf16.f32 "
                 "{%0,%1,%2,%3}, {%4,%5,%6,%7}, {%8,%9}, {%0,%1,%2,%3};"
                 : "+f"(c[0]), "+f"(c[1]), "+f"(c[2]), "+f"(c[3])
                 : "r"(a[0]), "r"(a[1]), "r"(a[2]), "r"(a[3]), "r"(b[0]), "r"(b[1]));
}
__device__ __forceinline__ void split_bf16(float v, __nv_bfloat16& h, __nv_bfloat16& l) {
    h = __float2bfloat16_rn(v);
    l = __float2bfloat16_rn(v - __bfloat162float(h));
}

// ------------------- zero counter -------------------
__global__ void k_zero1() { if (threadIdx.x == 0) g_flagcnt[0] = 0; }

// ------------------- W_in split + transpose -> WT hi/lo [256][1408] bf16 -------------
__global__ __launch_bounds__(256) void k_wprep(const float* __restrict__ Win) {
    __shared__ float tile[32][33];
    const int r0 = blockIdx.x * 32, c0 = blockIdx.y * 32;
    const int tx = threadIdx.x & 31, ty = threadIdx.x >> 5;
    for (int rr = ty; rr < 32; rr += 8)
        tile[rr][tx] = Win[(size_t)(r0 + rr) * P_DIM + c0 + tx];
    __syncthreads();
    for (int rr = ty; rr < 32; rr += 8) {
        __nv_bfloat16 h, l;
        split_bf16(tile[tx][rr], h, l);
        g_WhiT[(size_t)(c0 + rr) * D_DIM + r0 + tx] = h;
        g_WloT[(size_t)(c0 + rr) * D_DIM + r0 + tx] = l;
    }
}

// ------------------- codebook split -------------------
__global__ __launch_bounds__(256) void k_cbprep(const float* __restrict__ e0,
                                                const float* __restrict__ e1,
                                                const float* __restrict__ e2) {
    const int row = blockIdx.x;
    const float* src = (row < KC0) ? (e0 + (size_t)row * P_DIM)
                     : (row < KC0 + KC1) ? (e1 + (size_t)(row - KC0) * P_DIM)
                                         : (e2 + (size_t)(row - KC0 - KC1) * P_DIM);
    const int p = threadIdx.x;
    __nv_bfloat16 h, l;
    split_bf16(src[p], h, l);
    g_cbh[row * P_DIM + p] = h;
    g_cbl[row * P_DIM + p] = l;
}

// ------------------- ssq: exact fp32 sequential order, parallel rows ------------------
__global__ __launch_bounds__(256) void k_ssqE(const float* __restrict__ e0,
                                              const float* __restrict__ e1,
                                              const float* __restrict__ e2) {
    __shared__ float buf[8][260];
    const int warp = threadIdx.x >> 5, lane = threadIdx.x & 31;
    const int r = blockIdx.x * 8 + warp;
    if (r >= KT) return;
    const float* src = (r < KC0) ? (e0 + (size_t)r * P_DIM)
                     : (r < KC0 + KC1) ? (e1 + (size_t)(r - KC0) * P_DIM)
                                       : (e2 + (size_t)(r - KC0 - KC1) * P_DIM);
#pragma unroll
    for (int k = 0; k < 8; k++) buf[warp][lane + 32 * k] = src[lane + 32 * k];
    __syncwarp();
    if (lane == 0) {
        float s = 0.f;
        for (int p = 0; p < P_DIM; p++) s = __fadd_rn(s, __fmul_rn(buf[warp][p], buf[warp][p]));
        g_ssq[r] = s;
    }
}

// ------------------- Gram tables G01,G02,G12 (fp32 warp dots) -------------------
__global__ __launch_bounds__(256) void k_tables(const float* __restrict__ e0,
                                                const float* __restrict__ e1,
                                                const float* __restrict__ e2) {
    int gw = (blockIdx.x * 256 + threadIdx.x) >> 5;
    int lane = threadIdx.x & 31;
    if (gw >= 57344) return;       // 8192 + 16384 + 32768
    const float *a, *b;
    float* dst;
    if (gw < 8192) {
        a = e0 + (size_t)(gw >> 7) * P_DIM;
        b = e1 + (size_t)(gw & 127) * P_DIM;
        dst = g_G01 + gw;
    } else if (gw < 24576) {
        int id = gw - 8192;
        a = e0 + (size_t)(id >> 8) * P_DIM;
        b = e2 + (size_t)(id & 255) * P_DIM;
        dst = g_G02 + id;
    } else {
        int id = gw - 24576;
        a = e1 + (size_t)(id >> 8) * P_DIM;
        b = e2 + (size_t)(id & 255) * P_DIM;
        dst = g_G12 + id;
    }
    float s = 0.f;
#pragma unroll
    for (int k = 0; k < 8; k++) s += a[lane + 32 * k] * b[lane + 32 * k];
#pragma unroll
    for (int o = 16; o; o >>= 1) s += __shfl_xor_sync(0xffffffffu, s, o);
    if (lane == 0) *dst = s;
}

// ------------------- GEMM1 via mma.sync bf16x3 (proven R7) ---------------------------
__global__ __launch_bounds__(256, 1) void k_gemm1_mma(const float* __restrict__ z,
                                                      const float* __restrict__ bin) {
    __shared__ __nv_bfloat16 Ah[128][40], Al[128][40], Bh[128][40], Bl[128][40];
    const int tid = threadIdx.x, wid = tid >> 5, lane = tid & 31;
    const int warp_m = wid >> 2, warp_n = wid & 3;
    const size_t bm = (size_t)blockIdx.y * 128;
    const int bnG = blockIdx.x * 128;
    const uint32_t sAh = smem_u32(Ah), sAl = smem_u32(Al);
    const uint32_t sBh = smem_u32(Bh), sBl = smem_u32(Bl);
    const int g = lane >> 3, lr = lane & 7;

    float acc[4][4][4];
#pragma unroll
    for (int mt = 0; mt < 4; mt++)
#pragma unroll
        for (int nt = 0; nt < 4; nt++)
#pragma unroll
            for (int q = 0; q < 4; q++) acc[mt][nt][q] = 0.f;

    for (int kc = 0; kc < D_DIM / 32; kc++) {
        const int k0 = kc * 32;
#pragma unroll
        for (int q = 0; q < 4; q++) {
            int i = tid + q * 256;
            int r = i >> 3, c4 = i & 7;
            float4 v = *(const float4*)(z + (bm + r) * D_DIM + k0 + c4 * 4);
            __nv_bfloat16 h0, l0, h1, l1, h2, l2, h3, l3;
            split_bf16(v.x, h0, l0); split_bf16(v.y, h1, l1);
            split_bf16(v.z, h2, l2); split_bf16(v.w, h3, l3);
            __nv_bfloat162 ph0 = __halves2bfloat162(h0, h1), ph1 = __halves2bfloat162(h2, h3);
            __nv_bfloat162 pl0 = __halves2bfloat162(l0, l1), pl1 = __halves2bfloat162(l2, l3);
            *(uint2*)&Ah[r][c4 * 4] = make_uint2(*(uint32_t*)&ph0, *(uint32_t*)&ph1);
            *(uint2*)&Al[r][c4 * 4] = make_uint2(*(uint32_t*)&pl0, *(uint32_t*)&pl1);
        }
#pragma unroll
        for (int q = 0; q < 2; q++) {
            int i = tid + q * 256;
            int n = i >> 2, c = i & 3;
            *(uint4*)&Bh[n][c * 8] = *(const uint4*)(g_WhiT + (size_t)(bnG + n) * D_DIM + k0 + c * 8);
            *(uint4*)&Bl[n][c * 8] = *(const uint4*)(g_WloT + (size_t)(bnG + n) * D_DIM + k0 + c * 8);
        }
        __syncthreads();
#pragma unroll
        for (int ks = 0; ks < 2; ks++) {
            const int kk = ks * 16;
            uint32_t bhf[4][2], blf[4][2];
#pragma unroll
            for (int p = 0; p < 2; p++) {
                const int n0 = warp_n * 32 + p * 16;
                uint32_t off = (uint32_t)((n0 + ((g >> 1) << 3) + lr) * 40 + kk + ((g & 1) << 3)) * 2;
                uint32_t t[4];
                ldm4(t, sBh + off);
                bhf[p * 2][0] = t[0]; bhf[p * 2][1] = t[1];
                bhf[p * 2 + 1][0] = t[2]; bhf[p * 2 + 1][1] = t[3];
                ldm4(t, sBl + off);
                blf[p * 2][0] = t[0]; blf[p * 2][1] = t[1];
                blf[p * 2 + 1][0] = t[2]; blf[p * 2 + 1][1] = t[3];
            }
#pragma unroll
            for (int mt = 0; mt < 4; mt++) {
                const int m0 = warp_m * 64 + mt * 16;
                uint32_t aoff = (uint32_t)((m0 + ((g & 1) << 3) + lr) * 40 + kk + ((g >> 1) << 3)) * 2;
                uint32_t ah[4], al[4];
                ldm4(ah, sAh + aoff);
                ldm4(al, sAl + aoff);
#pragma unroll
                for (int nt = 0; nt < 4; nt++) {
                    mma_bf16(acc[mt][nt], ah, bhf[nt]);
                    mma_bf16(acc[mt][nt], ah, blf[nt]);
                    mma_bf16(acc[mt][nt], al, bhf[nt]);
                }
            }
        }
        __syncthreads();
    }
#pragma unroll
    for (int mt = 0; mt < 4; mt++) {
        const size_t row = bm + warp_m * 64 + mt * 16 + (lane >> 2);
#pragma unroll
        for (int nt = 0; nt < 4; nt++) {
            const int col = bnG + warp_n * 32 + nt * 8 + ((lane & 3) << 1);
            float b0 = bin[col], b1 = bin[col + 1];
            *(float2*)(g_r + row * P_DIM + col) =
                make_float2(acc[mt][nt][0] + b0, acc[mt][nt][1] + b1);
            *(float2*)(g_r + (row + 8) * P_DIM + col) =
                make_float2(acc[mt][nt][2] + b0, acc[mt][nt][3] + b1);
        }
    }
}

// ------------------- single GEMMS: S = zproj @ emb_catT [T][448] ---------------------
__global__ __launch_bounds__(256, 1) void k_gemmS_mma() {
    __shared__ __nv_bfloat16 Ah[128][40], Al[128][40], Bh[64][40], Bl[64][40];
    const int tid = threadIdx.x, wid = tid >> 5, lane = tid & 31;
    const int warp_m = wid >> 1, warp_n = wid & 1;
    const size_t bm = (size_t)blockIdx.y * 128;
    const int bn = blockIdx.x * 64;
    const uint32_t sAh = smem_u32(Ah), sAl = smem_u32(Al);
    const uint32_t sBh = smem_u32(Bh), sBl = smem_u32(Bl);
    const int g = lane >> 3, lr = lane & 7;

    float acc[2][4][4];
#pragma unroll
    for (int mt = 0; mt < 2; mt++)
#pragma unroll
        for (int nt = 0; nt < 4; nt++)
#pragma unroll
            for (int q = 0; q < 4; q++) acc[mt][nt][q] = 0.f;

    for (int kc = 0; kc < P_DIM / 32; kc++) {
        const int k0 = kc * 32;
#pragma unroll
        for (int q = 0; q < 4; q++) {
            int i = tid + q * 256;
            int r = i >> 3, c4 = i & 7;
            float4 v = *(const float4*)(g_r + (bm + r) * P_DIM + k0 + c4 * 4);
            __nv_bfloat16 h0, l0, h1, l1, h2, l2, h3, l3;
            split_bf16(v.x, h0, l0); split_bf16(v.y, h1, l1);
            split_bf16(v.z, h2, l2); split_bf16(v.w, h3, l3);
            __nv_bfloat162 ph0 = __halves2bfloat162(h0, h1), ph1 = __halves2bfloat162(h2, h3);
            __nv_bfloat162 pl0 = __halves2bfloat162(l0, l1), pl1 = __halves2bfloat162(l2, l3);
            *(uint2*)&Ah[r][c4 * 4] = make_uint2(*(uint32_t*)&ph0, *(uint32_t*)&ph1);
            *(uint2*)&Al[r][c4 * 4] = make_uint2(*(uint32_t*)&pl0, *(uint32_t*)&pl1);
        }
        {
            int n = tid >> 2, c = tid & 3;
            *(uint4*)&Bh[n][c * 8] = *(const uint4*)(g_cbh + (size_t)(bn + n) * P_DIM + k0 + c * 8);
            *(uint4*)&Bl[n][c * 8] = *(const uint4*)(g_cbl + (size_t)(bn + n) * P_DIM + k0 + c * 8);
        }
        __syncthreads();
#pragma unroll
        for (int ks = 0; ks < 2; ks++) {
            const int kk = ks * 16;
            uint32_t bhf[4][2], blf[4][2];
#pragma unroll
            for (int p = 0; p < 2; p++) {
                const int n0 = warp_n * 32 + p * 16;
                uint32_t off = (uint32_t)((n0 + ((g >> 1) << 3) + lr) * 40 + kk + ((g & 1) << 3)) * 2;
                uint32_t t[4];
                ldm4(t, sBh + off);
                bhf[p * 2][0] = t[0]; bhf[p * 2][1] = t[1];
                bhf[p * 2 + 1][0] = t[2]; bhf[p * 2 + 1][1] = t[3];
                ldm4(t, sBl + off);
                blf[p * 2][0] = t[0]; blf[p * 2][1] = t[1];
                blf[p * 2 + 1][0] = t[2]; blf[p * 2 + 1][1] = t[3];
            }
#pragma unroll
            for (int mt = 0; mt < 2; mt++) {
                const int m0 = warp_m * 32 + mt * 16;
                uint32_t aoff = (uint32_t)((m0 + ((g & 1) << 3) + lr) * 40 + kk + ((g >> 1) << 3)) * 2;
                uint32_t ah[4], al[4];
                ldm4(ah, sAh + aoff);
                ldm4(al, sAl + aoff);
#pragma unroll
                for (int nt = 0; nt < 4; nt++) {
                    mma_bf16(acc[mt][nt], ah, bhf[nt]);
                    mma_bf16(acc[mt][nt], ah, blf[nt]);
                    mma_bf16(acc[mt][nt], al, bhf[nt]);
                }
            }
        }
        __syncthreads();
    }
#pragma unroll
    for (int mt = 0; mt < 2; mt++) {
        const size_t row = bm + warp_m * 32 + mt * 16 + (lane >> 2);
#pragma unroll
        for (int nt = 0; nt < 4; nt++) {
            const int col = bn + warp_n * 32 + nt * 8 + ((lane & 3) << 1);
            *(float2*)(g_S + row * KT + col) = make_float2(acc[mt][nt][0], acc[mt][nt][1]);
            *(float2*)(g_S + (row + 8) * KT + col) = make_float2(acc[mt][nt][2], acc[mt][nt][3]);
        }
    }
}

// ------------------- ssr (fast-path loss only; warp-reduced fp32) --------------------
__global__ __launch_bounds__(256) void k_ssr() {
    const int warp = threadIdx.x >> 5, lane = threadIdx.x & 31;
    const size_t t = (size_t)blockIdx.x * 8 + warp;
    const float* rr = g_r + t * P_DIM;
    float s = 0.f;
#pragma unroll
    for (int k = 0; k < 8; k++) { float v = rr[lane + 32 * k]; s += v * v; }
#pragma unroll
    for (int o = 16; o; o >>= 1) s += __shfl_xor_sync(0xffffffffu, s, o);
    if (lane == 0) g_ssr[t] = s;
}

// ------------------- cascade pick (read-only, Gram-corrected, gap-certified) ---------
__device__ __forceinline__ void top2_reduce(float& m1, float& m2, int& i1) {
#pragma unroll
    for (int o = 16; o; o >>= 1) {
        float om1 = __shfl_xor_sync(0xffffffffu, m1, o);
        int   oi1 = __shfl_xor_sync(0xffffffffu, i1, o);
        float om2 = __shfl_xor_sync(0xffffffffu, m2, o);
        if (om1 < m1 || (om1 == m1 && oi1 < i1)) { m2 = fminf(m1, om2); m1 = om1; i1 = oi1; }
        else m2 = fminf(m2, om1);
    }
}

__global__ __launch_bounds__(256) void k_pickcas(float* __restrict__ out_idxf) {
    __shared__ float ssq_s[KT];
    for (int i = threadIdx.x; i < KT; i += 256) ssq_s[i] = g_ssq[i];
    __syncthreads();
    const int warp = threadIdx.x >> 5, lane = threadIdx.x & 31;
    const int t = blockIdx.x * 8 + warp;
    const float* Srow = g_S + (size_t)t * KT;

    // level 0 (K=64)
    float m1 = CUDART_INF_F, m2 = CUDART_INF_F; int i1 = 0x7fffffff;
#pragma unroll
    for (int kc = 0; kc < 2; kc++) {
        int j = kc * 32 + lane;
        float d = ssq_s[j] - 2.0f * Srow[j];
        if (d < m1) { m2 = m1; m1 = d; i1 = j; } else m2 = fminf(m2, d);
    }
    top2_reduce(m1, m2, i1);
    const int i0 = i1; const float mv0 = m1, gap0 = m2 - m1;

    // level 1 (K=128): d = ssq - 2(S - G01[i0,j])
    const float* g01 = g_G01 + i0 * KC1;
    m1 = CUDART_INF_F; m2 = CUDART_INF_F; i1 = 0x7fffffff;
#pragma unroll
    for (int kc = 0; kc < 4; kc++) {
        int j = kc * 32 + lane;
        float d = ssq_s[KC0 + j] - 2.0f * (Srow[KC0 + j] - g01[j]);
        if (d < m1) { m2 = m1; m1 = d; i1 = j; } else m2 = fminf(m2, d);
    }
    top2_reduce(m1, m2, i1);
    const int idx1 = i1; const float mv1 = m1, gap1 = m2 - m1;

    // level 2 (K=256): d = ssq - 2(S - G02[i0,j] - G12[i1,j])
    const float* g02 = g_G02 + i0 * KC2;
    const float* g12 = g_G12 + idx1 * KC2;
    m1 = CUDART_INF_F; m2 = CUDART_INF_F; i1 = 0x7fffffff;
#pragma unroll
    for (int kc = 0; kc < 8; kc++) {
        int j = kc * 32 + lane;
        float d = ssq_s[KC0 + KC1 + j] - 2.0f * (Srow[KC0 + KC1 + j] - g02[j] - g12[j]);
        if (d < m1) { m2 = m1; m1 = d; i1 = j; } else m2 = fminf(m2, d);
    }
    top2_reduce(m1, m2, i1);
    const int idx2 = i1; const float mv2 = m1, gap2 = m2 - m1;

    if (lane == 0) {
        g_idx[t] = i0; g_idx[T_TOK + t] = idx1; g_idx[2 * T_TOK + t] = idx2;
        out_idxf[t] = (float)i0;
        out_idxf[T_TOK + t] = (float)idx1;
        out_idxf[2 * T_TOK + t] = (float)idx2;
        g_flagged[t] = (gap0 < TAU || gap1 < TAU || gap2 < TAU) ? 1 : 0;
        float s = g_ssr[t];
        // loss = ||r1||^2+||r2||^2+||r3||^2 = 3s+3m0+2m1+m2
        g_losstok[t] = 3.f * s + 3.f * mv0 + 2.f * mv1 + mv2;
    }
}

// ------------------- compact flag list -------------------
__global__ __launch_bounds__(256) void k_compact() {
    int i = blockIdx.x * 256 + threadIdx.x;
    for (; i < T_TOK; i += gridDim.x * 256)
        if (g_flagged[i]) g_flaglist[atomicAdd(&g_flagcnt[0], 1)] = i;
}

// ------------------- fixup A: exact zproj for flagged tokens (proven R7) -------------
__global__ __launch_bounds__(256, 1) void k_fixA(const float* __restrict__ z,
                                                 const float* __restrict__ Win,
                                                 const float* __restrict__ bin) {
    extern __shared__ char sm[];
    float* zsm = (float*)sm;                 // [32][68]
    float* Wsm = (float*)(sm + 32 * 68 * 4); // [64][256]
    __shared__ int tl[32];
    const int tid = threadIdx.x;
    const int cnt = g_flagcnt[0];
    if (cnt == 0) return;

    for (int base = blockIdx.x * 32; base < cnt; base += gridDim.x * 32) {
        if (tid < 32) tl[tid] = g_flaglist[min(base + tid, cnt - 1)];
        __syncthreads();
        const int tg = tid >> 5, cg = tid & 31;
        float acc[4][8];
#pragma unroll
        for (int a = 0; a < 4; a++)
#pragma unroll
            for (int b = 0; b < 8; b++) acc[a][b] = 0.f;

        for (int kc = 0; kc < D_DIM / 64; kc++) {
#pragma unroll
            for (int q = 0; q < 2; q++) {
                int i = tid + q * 256;
                int s = i >> 4, c4 = i & 15;
                *(float4*)(zsm + s * 68 + c4 * 4) =
                    *(const float4*)(z + (size_t)tl[s] * D_DIM + kc * 64 + c4 * 4);
            }
#pragma unroll
            for (int q = 0; q < 16; q++) {
                int i = tid + q * 256;
                int k = i >> 6, c4 = i & 63;
                *(float4*)(Wsm + k * 256 + c4 * 4) =
                    *(const float4*)(Win + (size_t)(kc * 64 + k) * P_DIM + c4 * 4);
            }
            __syncthreads();
            for (int k = 0; k < 64; k++) {
                float4 w0 = *(const float4*)(Wsm + k * 256 + cg * 8);
                float4 w1 = *(const float4*)(Wsm + k * 256 + cg * 8 + 4);
                float wv[8] = {w0.x, w0.y, w0.z, w0.w, w1.x, w1.y, w1.z, w1.w};
#pragma unroll
                for (int a = 0; a < 4; a++) {
                    float zv = zsm[(tg * 4 + a) * 68 + k];
#pragma unroll
                    for (int b = 0; b < 8; b++)
                        acc[a][b] = __fmaf_rn(zv, wv[b], acc[a][b]);
                }
            }
            __syncthreads();
        }
#pragma unroll
        for (int a = 0; a < 4; a++) {
            int s = tg * 4 + a;
            if (base + s < cnt) {
                float* dst = g_S + (size_t)tl[s] * P_DIM;
#pragma unroll
                for (int b = 0; b < 8; b++)
                    dst[cg * 8 + b] = __fadd_rn(acc[a][b], bin[cg * 8 + b]);
            }
        }
        __syncthreads();
    }
}

// ------------------- fixup B: exact cascade (Round-3 arithmetic, proven) -------------
__global__ __launch_bounds__(256, 1) void k_fixB(const float* __restrict__ e0,
                                                 const float* __restrict__ e1,
                                                 const float* __restrict__ e2,
                                                 float* __restrict__ out_idxf) {
    extern __shared__ char sm[];
    float* r8  = (float*)sm;                                  // [8][257]
    float* cbs = (float*)(sm + 8 * 257 * 4);                  // [128][257]
    float* Ssm = (float*)(sm + 8 * 257 * 4 + 128 * 257 * 4);  // [8][256]
    __shared__ float ssr8[8];
    __shared__ int tl[8];
    const int tid = threadIdx.x, warp = tid >> 5, lane = tid & 31;
    const int cnt = g_flagcnt[0];
    if (cnt == 0) return;
    const float* cbl_[3] = {e0, e1, e2};
    const int Kl[3] = {KC0, KC1, KC2};
    const int offl[3] = {0, KC0, KC0 + KC1};

    for (int base = blockIdx.x * 8; base < cnt; base += gridDim.x * 8) {
        if (tid < 8) tl[tid] = g_flaglist[min(base + tid, cnt - 1)];
        __syncthreads();
        for (int i = tid; i < 8 * 256; i += 256)
            r8[(i >> 8) * 257 + (i & 255)] = g_S[(size_t)tl[i >> 8] * P_DIM + (i & 255)];
        __syncthreads();
        if (tid < 8) {
            float s = 0.f;
            for (int p = 0; p < P_DIM; p++)
                s = __fadd_rn(s, __fmul_rn(r8[tid * 257 + p], r8[tid * 257 + p]));
            ssr8[tid] = s;
        }
        __syncthreads();

        int myidx[3];
        double lsd = 0.0;
        for (int lvl = 0; lvl < 3; lvl++) {
            const int K = Kl[lvl];
            const float* cb = cbl_[lvl];
            for (int ch = 0; ch < (K + 127) / 128; ch++) {
                const int rows = min(128, K - ch * 128);
                for (int i = tid; i < rows * 256; i += 256)
                    cbs[(i >> 8) * 257 + (i & 255)] =
                        cb[(size_t)(ch * 128 + (i >> 8)) * P_DIM + (i & 255)];
                __syncthreads();
                for (int m = 0; m < rows / 32; m++) {
                    int jl = m * 32 + lane;
                    float a = 0.f;
                    for (int p = 0; p < P_DIM; p++)
                        a = __fmaf_rn(r8[warp * 257 + p], cbs[jl * 257 + p], a);
                    Ssm[warp * 256 + ch * 128 + jl] = a;
                }
                __syncthreads();
            }
            const float ssr = ssr8[warp];
            float best = CUDART_INF_F;
            int bi = 0x7fffffff;
            for (int kc = 0; kc < K / 32; kc++) {
                int j = kc * 32 + lane;
                float d = __fadd_rn(__fsub_rn(ssr, 2.0f * Ssm[warp * 256 + j]),
                                    g_ssq[offl[lvl] + j]);
                if (d < best) { best = d; bi = j; }
            }
#pragma unroll
            for (int o = 16; o; o >>= 1) {
                float od = __shfl_xor_sync(0xffffffffu, best, o);
                int   oi = __shfl_xor_sync(0xffffffffu, bi, o);
                if (od < best || (od == best && oi < bi)) { best = od; bi = oi; }
            }
            myidx[lvl] = bi;
            const float* er = cb + (size_t)bi * P_DIM;
            double lp = 0.0;
#pragma unroll
            for (int k = 0; k < 8; k++) {
                int p = lane + 32 * k;
                float nv = __fsub_rn(r8[warp * 257 + p], er[p]);
                r8[warp * 257 + p] = nv;
                lp += (double)nv * (double)nv;
            }
#pragma unroll
            for (int o = 16; o; o >>= 1) lp += __shfl_xor_sync(0xffffffffu, lp, o);
            lsd += lp;
            __syncwarp();
            if (lane == 0 && lvl < 2) {
                float s = 0.f;
                for (int p = 0; p < P_DIM; p++)
                    s = __fadd_rn(s, __fmul_rn(r8[warp * 257 + p], r8[warp * 257 + p]));
                ssr8[warp] = s;
            }
            __syncthreads();
        }
        if (lane == 0 && base + warp < cnt) {
            int t = tl[warp];
            g_idx[t] = myidx[0]; g_idx[T_TOK + t] = myidx[1]; g_idx[2 * T_TOK + t] = myidx[2];
            out_idxf[t] = (float)myidx[0];
            out_idxf[T_TOK + t] = (float)myidx[1];
            out_idxf[2 * T_TOK + t] = (float)myidx[2];
            g_losstok[t] = (float)lsd;
        }
        __syncthreads();
    }
}

// ------------------- loss reduce -------------------
__global__ __launch_bounds__(256) void k_lossred(float* __restrict__ out_loss) {
    __shared__ double smm[256];
    double s = 0.0;
    for (int i = threadIdx.x; i < T_TOK; i += 256) s += (double)g_losstok[i];
    smm[threadIdx.x] = s;
    __syncthreads();
    for (int o = 128; o; o >>= 1) {
        if (threadIdx.x < o) smm[threadIdx.x] += smm[threadIdx.x + o];
        __syncthreads();
    }
    if (threadIdx.x == 0)
        *out_loss = (float)(smm[0] * (0.25 / (3.0 * (double)T_TOK * (double)P_DIM)));
}

// ------------------- EW = emb_cat @ W_out -------------------
__global__ __launch_bounds__(256) void k_ew(const float* __restrict__ e0,
                                            const float* __restrict__ e1,
                                            const float* __restrict__ e2,
                                            const float* __restrict__ Wout) {
    __shared__ float a[8][P_DIM];
    const int rbase = blockIdx.x * 8;
    for (int i = threadIdx.x; i < 8 * P_DIM; i += 256) {
        int r = rbase + i / P_DIM, p = i % P_DIM;
        const float* s = (r < KC0) ? (e0 + (size_t)r * P_DIM)
                       : (r < KC0 + KC1) ? (e1 + (size_t)(r - KC0) * P_DIM)
                                         : (e2 + (size_t)(r - KC0 - KC1) * P_DIM);
        a[i / P_DIM][p] = s[p];
    }
    __syncthreads();
    for (int c = threadIdx.x; c < D_DIM; c += 256) {
        float acc[8] = {0.f, 0.f, 0.f, 0.f, 0.f, 0.f, 0.f, 0.f};
        for (int p = 0; p < P_DIM; p++) {
            float w = Wout[(size_t)p * D_DIM + c];
#pragma unroll
            for (int r = 0; r < 8; r++) acc[r] = __fmaf_rn(a[r][p], w, acc[r]);
        }
#pragma unroll
        for (int r = 0; r < 8; r++) g_EW[(size_t)(rbase + r) * D_DIM + c] = acc[r];
    }
}

// ------------------- output gather -------------------
__global__ __launch_bounds__(352) void k_out(const float* __restrict__ bout,
                                             float* __restrict__ out) {
    const int t = blockIdx.x;
    const int i0 = g_idx[t], i1 = g_idx[T_TOK + t], i2 = g_idx[2 * T_TOK + t];
    const float4* r0 = (const float4*)(g_EW + (size_t)i0 * D_DIM);
    const float4* r1 = (const float4*)(g_EW + (size_t)(KC0 + i1) * D_DIM);
    const float4* r2 = (const float4*)(g_EW + (size_t)(KC0 + KC1 + i2) * D_DIM);
    const float4* bb = (const float4*)bout;
    float4* o = (float4*)(out + (size_t)t * D_DIM);
    const int c = threadIdx.x;
    float4 a = r0[c], b = r1[c], cc = r2[c], d = bb[c];
    o[c] = make_float4(a.x + b.x + cc.x + d.x, a.y + b.y + cc.y + d.y,
                       a.z + b.z + cc.z + d.z, a.w + b.w + cc.w + d.w);
}

// ------------------- launch -------------------
extern "C" void kernel_launch(void* const* d_in, const int* in_sizes, int n_in,
                              void* d_out, int out_size) {
    const float* z     = (const float*)d_in[0];
    const float* W_in  = (const float*)d_in[1];
    const float* b_in  = (const float*)d_in[2];
    const float* W_out = (const float*)d_in[3];
    const float* b_out = (const float*)d_in[4];
    const float* e0    = (const float*)d_in[5];
    const float* e1    = (const float*)d_in[6];
    const float* e2    = (const float*)d_in[7];

    float* out      = (float*)d_out;
    float* out_idxf = out + (size_t)T_TOK * D_DIM;
    float* out_loss = out_idxf + 3 * T_TOK;

    cudaFuncSetAttribute(k_fixA, cudaFuncAttributeMaxDynamicSharedMemorySize,
                         32 * 68 * 4 + 64 * 256 * 4);
    cudaFuncSetAttribute(k_fixB, cudaFuncAttributeMaxDynamicSharedMemorySize,
                         8 * 257 * 4 + 128 * 257 * 4 + 8 * 256 * 4);

    k_zero1<<<1, 32>>>();
    k_wprep<<<dim3(D_DIM / 32, P_DIM / 32), 256>>>(W_in);
    k_cbprep<<<KT, 256>>>(e0, e1, e2);
    k_ssqE<<<(KT + 7) / 8, 256>>>(e0, e1, e2);
    k_tables<<<7168, 256>>>(e0, e1, e2);
    k_ew<<<KT / 8, 256>>>(e0, e1, e2, W_out);

    k_gemm1_mma<<<dim3(2, T_TOK / 128), 256>>>(z, b_in);
    k_ssr<<<T_TOK / 8, 256>>>();
    k_gemmS_mma<<<dim3(KT / 64, T_TOK / 128), 256>>>();
    k_pickcas<<<T_TOK / 8, 256>>>(out_idxf);

    k_compact<<<64, 256>>>();
    k_fixA<<<256, 256, 32 * 68 * 4 + 64 * 256 * 4>>>(z, W_in, b_in);
    k_fixB<<<512, 256, 8 * 257 * 4 + 128 * 257 * 4 + 8 * 256 * 4>>>(e0, e1, e2, out_idxf);

    k_lossred<<<1, 256>>>(out_loss);
    k_out<<<T_TOK, 352>>>(b_out, out);
}

// round 10
// speedup vs baseline: 1.1682x; 1.0158x over previous
#include <cuda_runtime.h>
#include <cuda_bf16.h>
#include <math_constants.h>
#include <cstdint>

#define T_TOK 32768
#define D_DIM 1408
#define P_DIM 256
#define KC0 64
#define KC1 128
#define KC2 256
#define KT  448
#define TAU 3e-3f

// ------------------- device scratch -------------------
static __device__ float  g_r[(size_t)T_TOK * P_DIM];
static __device__ float  g_S[(size_t)T_TOK * KT];         // scores; later reused as exact-zproj store
static __device__ float  g_ssq[KT];
static __device__ float  g_ssr[T_TOK];
static __device__ float  g_G01[KC0 * KC1];
static __device__ float  g_G02[KC0 * KC2];
static __device__ float  g_G12[KC1 * KC2];
static __device__ float  g_EW[(size_t)KT * D_DIM];
static __device__ int    g_idx[3 * T_TOK];
static __device__ float  g_losstok[T_TOK];
static __device__ int    g_flagged[T_TOK];
static __device__ int    g_flagcnt[1];
static __device__ int    g_flaglist[T_TOK];
static __device__ __nv_bfloat16 g_WhiT[(size_t)P_DIM * D_DIM];
static __device__ __nv_bfloat16 g_WloT[(size_t)P_DIM * D_DIM];
static __device__ __nv_bfloat16 g_zhi[(size_t)T_TOK * D_DIM];
static __device__ __nv_bfloat16 g_zlo[(size_t)T_TOK * D_DIM];
static __device__ __nv_bfloat16 g_rh[(size_t)T_TOK * P_DIM];
static __device__ __nv_bfloat16 g_rl[(size_t)T_TOK * P_DIM];
static __device__ __nv_bfloat16 g_cbh[KT * P_DIM];
static __device__ __nv_bfloat16 g_cbl[KT * P_DIM];

// ------------------- helpers -------------------
__device__ __forceinline__ uint32_t smem_u32(const void* p) {
    uint32_t a;
    asm("{ .reg .u64 t; cvta.to.shared.u64 t, %1; cvt.u32.u64 %0, t; }" : "=r"(a) : "l"(p));
    return a;
}
__device__ __forceinline__ void ldm4(uint32_t r[4], uint32_t a) {
    asm volatile("ldmatrix.sync.aligned.m8n8.x4.shared.b16 {%0,%1,%2,%3}, [%4];"
                 : "=r"(r[0]), "=r"(r[1]), "=r"(r[2]), "=r"(r[3]) : "r"(a));
}
__device__ __forceinline__ void mma_bf16(float c[4], const uint32_t a[4], const uint32_t b[2]) {
    asm volatile("mma.sync.aligned.m16n8k16.row.col.f32.bf16.bf16.f32 "
                 "{%0,%1,%2,%3}, {%4,%5,%6,%7}, {%8,%9}, {%0,%1,%2,%3};"
                 : "+f"(c[0]), "+f"(c[1]), "+f"(c[2]), "+f"(c[3])
                 : "r"(a[0]), "r"(a[1]), "r"(a[2]), "r"(a[3]), "r"(b[0]), "r"(b[1]));
}
__device__ __forceinline__ void split_bf16(float v, __nv_bfloat16& h, __nv_bfloat16& l) {
    h = __float2bfloat16_rn(v);
    l = __float2bfloat16_rn(v - __bfloat162float(h));
}

// ------------------- zero counter -------------------
__global__ void k_zero1() { if (threadIdx.x == 0) g_flagcnt[0] = 0; }

// ------------------- z pre-split: fp32 -> bf16 hi/lo -------------------
__global__ __launch_bounds__(256) void k_zprep(const float* __restrict__ z) {
    const size_t base = ((size_t)blockIdx.x * 256 + threadIdx.x) * 8;
    float4 v0 = *(const float4*)(z + base);
    float4 v1 = *(const float4*)(z + base + 4);
    float vv[8] = {v0.x, v0.y, v0.z, v0.w, v1.x, v1.y, v1.z, v1.w};
    __nv_bfloat16 h[8], l[8];
#pragma unroll
    for (int i = 0; i < 8; i++) split_bf16(vv[i], h[i], l[i]);
    __nv_bfloat162 ph[4], pl[4];
#pragma unroll
    for (int i = 0; i < 4; i++) {
        ph[i] = __halves2bfloat162(h[2 * i], h[2 * i + 1]);
        pl[i] = __halves2bfloat162(l[2 * i], l[2 * i + 1]);
    }
    *(uint4*)(g_zhi + base) = make_uint4(*(uint32_t*)&ph[0], *(uint32_t*)&ph[1],
                                         *(uint32_t*)&ph[2], *(uint32_t*)&ph[3]);
    *(uint4*)(g_zlo + base) = make_uint4(*(uint32_t*)&pl[0], *(uint32_t*)&pl[1],
                                         *(uint32_t*)&pl[2], *(uint32_t*)&pl[3]);
}

// ------------------- W_in split + transpose -------------------
__global__ __launch_bounds__(256) void k_wprep(const float* __restrict__ Win) {
    __shared__ float tile[32][33];
    const int r0 = blockIdx.x * 32, c0 = blockIdx.y * 32;
    const int tx = threadIdx.x & 31, ty = threadIdx.x >> 5;
    for (int rr = ty; rr < 32; rr += 8)
        tile[rr][tx] = Win[(size_t)(r0 + rr) * P_DIM + c0 + tx];
    __syncthreads();
    for (int rr = ty; rr < 32; rr += 8) {
        __nv_bfloat16 h, l;
        split_bf16(tile[tx][rr], h, l);
        g_WhiT[(size_t)(c0 + rr) * D_DIM + r0 + tx] = h;
        g_WloT[(size_t)(c0 + rr) * D_DIM + r0 + tx] = l;
    }
}

// ------------------- codebook split -------------------
__global__ __launch_bounds__(256) void k_cbprep(const float* __restrict__ e0,
                                                const float* __restrict__ e1,
                                                const float* __restrict__ e2) {
    const int row = blockIdx.x;
    const float* src = (row < KC0) ? (e0 + (size_t)row * P_DIM)
                     : (row < KC0 + KC1) ? (e1 + (size_t)(row - KC0) * P_DIM)
                                         : (e2 + (size_t)(row - KC0 - KC1) * P_DIM);
    const int p = threadIdx.x;
    __nv_bfloat16 h, l;
    split_bf16(src[p], h, l);
    g_cbh[row * P_DIM + p] = h;
    g_cbl[row * P_DIM + p] = l;
}

// ------------------- ssq (exact fp32 sequential order) -------------------
__global__ __launch_bounds__(256) void k_ssqE(const float* __restrict__ e0,
                                              const float* __restrict__ e1,
                                              const float* __restrict__ e2) {
    __shared__ float buf[8][260];
    const int warp = threadIdx.x >> 5, lane = threadIdx.x & 31;
    const int r = blockIdx.x * 8 + warp;
    if (r >= KT) return;
    const float* src = (r < KC0) ? (e0 + (size_t)r * P_DIM)
                     : (r < KC0 + KC1) ? (e1 + (size_t)(r - KC0) * P_DIM)
                                       : (e2 + (size_t)(r - KC0 - KC1) * P_DIM);
#pragma unroll
    for (int k = 0; k < 8; k++) buf[warp][lane + 32 * k] = src[lane + 32 * k];
    __syncwarp();
    if (lane == 0) {
        float s = 0.f;
        for (int p = 0; p < P_DIM; p++) s = __fadd_rn(s, __fmul_rn(buf[warp][p], buf[warp][p]));
        g_ssq[r] = s;
    }
}

// ------------------- Gram tables -------------------
__global__ __launch_bounds__(256) void k_tables(const float* __restrict__ e0,
                                                const float* __restrict__ e1,
                                                const float* __restrict__ e2) {
    int gw = (blockIdx.x * 256 + threadIdx.x) >> 5;
    int lane = threadIdx.x & 31;
    if (gw >= 57344) return;
    const float *a, *b;
    float* dst;
    if (gw < 8192) {
        a = e0 + (size_t)(gw >> 7) * P_DIM;
        b = e1 + (size_t)(gw & 127) * P_DIM;
        dst = g_G01 + gw;
    } else if (gw < 24576) {
        int id = gw - 8192;
        a = e0 + (size_t)(id >> 8) * P_DIM;
        b = e2 + (size_t)(id & 255) * P_DIM;
        dst = g_G02 + id;
    } else {
        int id = gw - 24576;
        a = e1 + (size_t)(id >> 8) * P_DIM;
        b = e2 + (size_t)(id & 255) * P_DIM;
        dst = g_G12 + id;
    }
    float s = 0.f;
#pragma unroll
    for (int k = 0; k < 8; k++) s += a[lane + 32 * k] * b[lane + 32 * k];
#pragma unroll
    for (int o = 16; o; o >>= 1) s += __shfl_xor_sync(0xffffffffu, s, o);
    if (lane == 0) *dst = s;
}

// ------------------- GEMM1: pre-split bf16, reg-staged pipeline ----------------------
__global__ __launch_bounds__(256, 1) void k_gemm1_mma(const float* __restrict__ bin) {
    __shared__ __nv_bfloat16 Ah[128][40], Al[128][40], Bh[128][40], Bl[128][40];
    const int tid = threadIdx.x, wid = tid >> 5, lane = tid & 31;
    const int warp_m = wid >> 2, warp_n = wid & 3;
    const size_t bm = (size_t)blockIdx.y * 128;
    const int bnG = blockIdx.x * 128;
    const uint32_t sAh = smem_u32(Ah), sAl = smem_u32(Al);
    const uint32_t sBh = smem_u32(Bh), sBl = smem_u32(Bl);
    const int g = lane >> 3, lr = lane & 7;
    // load slots: i = tid*2+q over 512: row=i>>2, chunk=i&3 (8 bf16 = 16B each)
    const int l_r0 = (tid * 2) >> 2, l_c0 = (tid * 2) & 3;
    const int l_r1 = (tid * 2 + 1) >> 2, l_c1 = (tid * 2 + 1) & 3;

    float acc[4][4][4];
#pragma unroll
    for (int mt = 0; mt < 4; mt++)
#pragma unroll
        for (int nt = 0; nt < 4; nt++)
#pragma unroll
            for (int q = 0; q < 4; q++) acc[mt][nt][q] = 0.f;

    uint4 rAh[2], rAl[2], rBh[2], rBl[2];
    auto load_tile = [&](int kc) {
        const int k0 = kc * 32;
        rAh[0] = *(const uint4*)(g_zhi + (bm + l_r0) * D_DIM + k0 + l_c0 * 8);
        rAh[1] = *(const uint4*)(g_zhi + (bm + l_r1) * D_DIM + k0 + l_c1 * 8);
        rAl[0] = *(const uint4*)(g_zlo + (bm + l_r0) * D_DIM + k0 + l_c0 * 8);
        rAl[1] = *(const uint4*)(g_zlo + (bm + l_r1) * D_DIM + k0 + l_c1 * 8);
        rBh[0] = *(const uint4*)(g_WhiT + (size_t)(bnG + l_r0) * D_DIM + k0 + l_c0 * 8);
        rBh[1] = *(const uint4*)(g_WhiT + (size_t)(bnG + l_r1) * D_DIM + k0 + l_c1 * 8);
        rBl[0] = *(const uint4*)(g_WloT + (size_t)(bnG + l_r0) * D_DIM + k0 + l_c0 * 8);
        rBl[1] = *(const uint4*)(g_WloT + (size_t)(bnG + l_r1) * D_DIM + k0 + l_c1 * 8);
    };
    auto store_tile = [&]() {
        *(uint4*)&Ah[l_r0][l_c0 * 8] = rAh[0];
        *(uint4*)&Ah[l_r1][l_c1 * 8] = rAh[1];
        *(uint4*)&Al[l_r0][l_c0 * 8] = rAl[0];
        *(uint4*)&Al[l_r1][l_c1 * 8] = rAl[1];
        *(uint4*)&Bh[l_r0][l_c0 * 8] = rBh[0];
        *(uint4*)&Bh[l_r1][l_c1 * 8] = rBh[1];
        *(uint4*)&Bl[l_r0][l_c0 * 8] = rBl[0];
        *(uint4*)&Bl[l_r1][l_c1 * 8] = rBl[1];
    };

    load_tile(0);
    for (int kc = 0; kc < D_DIM / 32; kc++) {
        store_tile();
        __syncthreads();
        if (kc + 1 < D_DIM / 32) load_tile(kc + 1);
#pragma unroll
        for (int ks = 0; ks < 2; ks++) {
            const int kk = ks * 16;
            uint32_t bhf[4][2], blf[4][2];
#pragma unroll
            for (int p = 0; p < 2; p++) {
                const int n0 = warp_n * 32 + p * 16;
                uint32_t off = (uint32_t)((n0 + ((g >> 1) << 3) + lr) * 40 + kk + ((g & 1) << 3)) * 2;
                uint32_t t[4];
                ldm4(t, sBh + off);
                bhf[p * 2][0] = t[0]; bhf[p * 2][1] = t[1];
                bhf[p * 2 + 1][0] = t[2]; bhf[p * 2 + 1][1] = t[3];
                ldm4(t, sBl + off);
                blf[p * 2][0] = t[0]; blf[p * 2][1] = t[1];
                blf[p * 2 + 1][0] = t[2]; blf[p * 2 + 1][1] = t[3];
            }
#pragma unroll
            for (int mt = 0; mt < 4; mt++) {
                const int m0 = warp_m * 64 + mt * 16;
                uint32_t aoff = (uint32_t)((m0 + ((g & 1) << 3) + lr) * 40 + kk + ((g >> 1) << 3)) * 2;
                uint32_t ah[4], al[4];
                ldm4(ah, sAh + aoff);
                ldm4(al, sAl + aoff);
#pragma unroll
                for (int nt = 0; nt < 4; nt++) {
                    mma_bf16(acc[mt][nt], ah, bhf[nt]);
                    mma_bf16(acc[mt][nt], ah, blf[nt]);
                    mma_bf16(acc[mt][nt], al, bhf[nt]);
                }
            }
        }
        __syncthreads();
    }
    // epilogue: fp32 + bias -> g_r, plus bf16 hi/lo split -> g_rh/g_rl
#pragma unroll
    for (int mt = 0; mt < 4; mt++) {
        const size_t row = bm + warp_m * 64 + mt * 16 + (lane >> 2);
#pragma unroll
        for (int nt = 0; nt < 4; nt++) {
            const int col = bnG + warp_n * 32 + nt * 8 + ((lane & 3) << 1);
            float b0 = bin[col], b1 = bin[col + 1];
            float v0 = acc[mt][nt][0] + b0, v1 = acc[mt][nt][1] + b1;
            float v2 = acc[mt][nt][2] + b0, v3 = acc[mt][nt][3] + b1;
            *(float2*)(g_r + row * P_DIM + col) = make_float2(v0, v1);
            *(float2*)(g_r + (row + 8) * P_DIM + col) = make_float2(v2, v3);
            __nv_bfloat16 h0, l0, h1, l1;
            split_bf16(v0, h0, l0); split_bf16(v1, h1, l1);
            __nv_bfloat162 ph = __halves2bfloat162(h0, h1), pl = __halves2bfloat162(l0, l1);
            *(uint32_t*)(g_rh + row * P_DIM + col) = *(uint32_t*)&ph;
            *(uint32_t*)(g_rl + row * P_DIM + col) = *(uint32_t*)&pl;
            split_bf16(v2, h0, l0); split_bf16(v3, h1, l1);
            ph = __halves2bfloat162(h0, h1); pl = __halves2bfloat162(l0, l1);
            *(uint32_t*)(g_rh + (row + 8) * P_DIM + col) = *(uint32_t*)&ph;
            *(uint32_t*)(g_rl + (row + 8) * P_DIM + col) = *(uint32_t*)&pl;
        }
    }
}

// ------------------- GEMMS: pre-split bf16, reg-staged pipeline ----------------------
__global__ __launch_bounds__(256, 1) void k_gemmS_mma() {
    __shared__ __nv_bfloat16 Ah[128][40], Al[128][40], Bh[64][40], Bl[64][40];
    const int tid = threadIdx.x, wid = tid >> 5, lane = tid & 31;
    const int warp_m = wid >> 1, warp_n = wid & 1;
    const size_t bm = (size_t)blockIdx.y * 128;
    const int bn = blockIdx.x * 64;
    const uint32_t sAh = smem_u32(Ah), sAl = smem_u32(Al);
    const uint32_t sBh = smem_u32(Bh), sBl = smem_u32(Bl);
    const int g = lane >> 3, lr = lane & 7;
    // A slots: 512 (128 rows x 4 chunks): 2/thread ; B slots: 256 (64 x 4): 1/thread
    const int a_r0 = (tid * 2) >> 2, a_c0 = (tid * 2) & 3;
    const int a_r1 = (tid * 2 + 1) >> 2, a_c1 = (tid * 2 + 1) & 3;
    const int b_r = tid >> 2, b_c = tid & 3;

    float acc[2][4][4];
#pragma unroll
    for (int mt = 0; mt < 2; mt++)
#pragma unroll
        for (int nt = 0; nt < 4; nt++)
#pragma unroll
            for (int q = 0; q < 4; q++) acc[mt][nt][q] = 0.f;

    uint4 rAh[2], rAl[2], rBh, rBl;
    auto load_tile = [&](int kc) {
        const int k0 = kc * 32;
        rAh[0] = *(const uint4*)(g_rh + (bm + a_r0) * P_DIM + k0 + a_c0 * 8);
        rAh[1] = *(const uint4*)(g_rh + (bm + a_r1) * P_DIM + k0 + a_c1 * 8);
        rAl[0] = *(const uint4*)(g_rl + (bm + a_r0) * P_DIM + k0 + a_c0 * 8);
        rAl[1] = *(const uint4*)(g_rl + (bm + a_r1) * P_DIM + k0 + a_c1 * 8);
        rBh = *(const uint4*)(g_cbh + (size_t)(bn + b_r) * P_DIM + k0 + b_c * 8);
        rBl = *(const uint4*)(g_cbl + (size_t)(bn + b_r) * P_DIM + k0 + b_c * 8);
    };
    auto store_tile = [&]() {
        *(uint4*)&Ah[a_r0][a_c0 * 8] = rAh[0];
        *(uint4*)&Ah[a_r1][a_c1 * 8] = rAh[1];
        *(uint4*)&Al[a_r0][a_c0 * 8] = rAl[0];
        *(uint4*)&Al[a_r1][a_c1 * 8] = rAl[1];
        *(uint4*)&Bh[b_r][b_c * 8] = rBh;
        *(uint4*)&Bl[b_r][b_c * 8] = rBl;
    };

    load_tile(0);
    for (int kc = 0; kc < P_DIM / 32; kc++) {
        store_tile();
        __syncthreads();
        if (kc + 1 < P_DIM / 32) load_tile(kc + 1);
#pragma unroll
        for (int ks = 0; ks < 2; ks++) {
            const int kk = ks * 16;
            uint32_t bhf[4][2], blf[4][2];
#pragma unroll
            for (int p = 0; p < 2; p++) {
                const int n0 = warp_n * 32 + p * 16;
                uint32_t off = (uint32_t)((n0 + ((g >> 1) << 3) + lr) * 40 + kk + ((g & 1) << 3)) * 2;
                uint32_t t[4];
                ldm4(t, sBh + off);
                bhf[p * 2][0] = t[0]; bhf[p * 2][1] = t[1];
                bhf[p * 2 + 1][0] = t[2]; bhf[p * 2 + 1][1] = t[3];
                ldm4(t, sBl + off);
                blf[p * 2][0] = t[0]; blf[p * 2][1] = t[1];
                blf[p * 2 + 1][0] = t[2]; blf[p * 2 + 1][1] = t[3];
            }
#pragma unroll
            for (int mt = 0; mt < 2; mt++) {
                const int m0 = warp_m * 32 + mt * 16;
                uint32_t aoff = (uint32_t)((m0 + ((g & 1) << 3) + lr) * 40 + kk + ((g >> 1) << 3)) * 2;
                uint32_t ah[4], al[4];
                ldm4(ah, sAh + aoff);
                ldm4(al, sAl + aoff);
#pragma unroll
                for (int nt = 0; nt < 4; nt++) {
                    mma_bf16(acc[mt][nt], ah, bhf[nt]);
                    mma_bf16(acc[mt][nt], ah, blf[nt]);
                    mma_bf16(acc[mt][nt], al, bhf[nt]);
                }
            }
        }
        __syncthreads();
    }
#pragma unroll
    for (int mt = 0; mt < 2; mt++) {
        const size_t row = bm + warp_m * 32 + mt * 16 + (lane >> 2);
#pragma unroll
        for (int nt = 0; nt < 4; nt++) {
            const int col = bn + warp_n * 32 + nt * 8 + ((lane & 3) << 1);
            *(float2*)(g_S + row * KT + col) = make_float2(acc[mt][nt][0], acc[mt][nt][1]);
            *(float2*)(g_S + (row + 8) * KT + col) = make_float2(acc[mt][nt][2], acc[mt][nt][3]);
        }
    }
}

// ------------------- ssr -------------------
__global__ __launch_bounds__(256) void k_ssr() {
    const int warp = threadIdx.x >> 5, lane = threadIdx.x & 31;
    const size_t t = (size_t)blockIdx.x * 8 + warp;
    const float* rr = g_r + t * P_DIM;
    float s = 0.f;
#pragma unroll
    for (int k = 0; k < 8; k++) { float v = rr[lane + 32 * k]; s += v * v; }
#pragma unroll
    for (int o = 16; o; o >>= 1) s += __shfl_xor_sync(0xffffffffu, s, o);
    if (lane == 0) g_ssr[t] = s;
}

// ------------------- cascade pick -------------------
__device__ __forceinline__ void top2_reduce(float& m1, float& m2, int& i1) {
#pragma unroll
    for (int o = 16; o; o >>= 1) {
        float om1 = __shfl_xor_sync(0xffffffffu, m1, o);
        int   oi1 = __shfl_xor_sync(0xffffffffu, i1, o);
        float om2 = __shfl_xor_sync(0xffffffffu, m2, o);
        if (om1 < m1 || (om1 == m1 && oi1 < i1)) { m2 = fminf(m1, om2); m1 = om1; i1 = oi1; }
        else m2 = fminf(m2, om1);
    }
}

__global__ __launch_bounds__(256) void k_pickcas(float* __restrict__ out_idxf) {
    __shared__ float ssq_s[KT];
    for (int i = threadIdx.x; i < KT; i += 256) ssq_s[i] = g_ssq[i];
    __syncthreads();
    const int warp = threadIdx.x >> 5, lane = threadIdx.x & 31;
    const int t = blockIdx.x * 8 + warp;
    const float* Srow = g_S + (size_t)t * KT;

    float m1 = CUDART_INF_F, m2 = CUDART_INF_F; int i1 = 0x7fffffff;
#pragma unroll
    for (int kc = 0; kc < 2; kc++) {
        int j = kc * 32 + lane;
        float d = ssq_s[j] - 2.0f * Srow[j];
        if (d < m1) { m2 = m1; m1 = d; i1 = j; } else m2 = fminf(m2, d);
    }
    top2_reduce(m1, m2, i1);
    const int i0 = i1; const float mv0 = m1, gap0 = m2 - m1;

    const float* g01 = g_G01 + i0 * KC1;
    m1 = CUDART_INF_F; m2 = CUDART_INF_F; i1 = 0x7fffffff;
#pragma unroll
    for (int kc = 0; kc < 4; kc++) {
        int j = kc * 32 + lane;
        float d = ssq_s[KC0 + j] - 2.0f * (Srow[KC0 + j] - g01[j]);
        if (d < m1) { m2 = m1; m1 = d; i1 = j; } else m2 = fminf(m2, d);
    }
    top2_reduce(m1, m2, i1);
    const int idx1 = i1; const float mv1 = m1, gap1 = m2 - m1;

    const float* g02 = g_G02 + i0 * KC2;
    const float* g12 = g_G12 + idx1 * KC2;
    m1 = CUDART_INF_F; m2 = CUDART_INF_F; i1 = 0x7fffffff;
#pragma unroll
    for (int kc = 0; kc < 8; kc++) {
        int j = kc * 32 + lane;
        float d = ssq_s[KC0 + KC1 + j] - 2.0f * (Srow[KC0 + KC1 + j] - g02[j] - g12[j]);
        if (d < m1) { m2 = m1; m1 = d; i1 = j; } else m2 = fminf(m2, d);
    }
    top2_reduce(m1, m2, i1);
    const int idx2 = i1; const float mv2 = m1, gap2 = m2 - m1;

    if (lane == 0) {
        g_idx[t] = i0; g_idx[T_TOK + t] = idx1; g_idx[2 * T_TOK + t] = idx2;
        out_idxf[t] = (float)i0;
        out_idxf[T_TOK + t] = (float)idx1;
        out_idxf[2 * T_TOK + t] = (float)idx2;
        g_flagged[t] = (gap0 < TAU || gap1 < TAU || gap2 < TAU) ? 1 : 0;
        float s = g_ssr[t];
        g_losstok[t] = 3.f * s + 3.f * mv0 + 2.f * mv1 + mv2;
    }
}

// ------------------- compact -------------------
__global__ __launch_bounds__(256) void k_compact() {
    int i = blockIdx.x * 256 + threadIdx.x;
    for (; i < T_TOK; i += gridDim.x * 256)
        if (g_flagged[i]) g_flaglist[atomicAdd(&g_flagcnt[0], 1)] = i;
}

// ------------------- fixup A (exact zproj) -------------------
__global__ __launch_bounds__(256, 1) void k_fixA(const float* __restrict__ z,
                                                 const float* __restrict__ Win,
                                                 const float* __restrict__ bin) {
    extern __shared__ char sm[];
    float* zsm = (float*)sm;
    float* Wsm = (float*)(sm + 32 * 68 * 4);
    __shared__ int tl[32];
    const int tid = threadIdx.x;
    const int cnt = g_flagcnt[0];
    if (cnt == 0) return;

    for (int base = blockIdx.x * 32; base < cnt; base += gridDim.x * 32) {
        if (tid < 32) tl[tid] = g_flaglist[min(base + tid, cnt - 1)];
        __syncthreads();
        const int tg = tid >> 5, cg = tid & 31;
        float acc[4][8];
#pragma unroll
        for (int a = 0; a < 4; a++)
#pragma unroll
            for (int b = 0; b < 8; b++) acc[a][b] = 0.f;

        for (int kc = 0; kc < D_DIM / 64; kc++) {
#pragma unroll
            for (int q = 0; q < 2; q++) {
                int i = tid + q * 256;
                int s = i >> 4, c4 = i & 15;
                *(float4*)(zsm + s * 68 + c4 * 4) =
                    *(const float4*)(z + (size_t)tl[s] * D_DIM + kc * 64 + c4 * 4);
            }
#pragma unroll
            for (int q = 0; q < 16; q++) {
                int i = tid + q * 256;
                int k = i >> 6, c4 = i & 63;
                *(float4*)(Wsm + k * 256 + c4 * 4) =
                    *(const float4*)(Win + (size_t)(kc * 64 + k) * P_DIM + c4 * 4);
            }
            __syncthreads();
            for (int k = 0; k < 64; k++) {
                float4 w0 = *(const float4*)(Wsm + k * 256 + cg * 8);
                float4 w1 = *(const float4*)(Wsm + k * 256 + cg * 8 + 4);
                float wv[8] = {w0.x, w0.y, w0.z, w0.w, w1.x, w1.y, w1.z, w1.w};
#pragma unroll
                for (int a = 0; a < 4; a++) {
                    float zv = zsm[(tg * 4 + a) * 68 + k];
#pragma unroll
                    for (int b = 0; b < 8; b++)
                        acc[a][b] = __fmaf_rn(zv, wv[b], acc[a][b]);
                }
            }
            __syncthreads();
        }
#pragma unroll
        for (int a = 0; a < 4; a++) {
            int s = tg * 4 + a;
            if (base + s < cnt) {
                float* dst = g_S + (size_t)tl[s] * P_DIM;
#pragma unroll
                for (int b = 0; b < 8; b++)
                    dst[cg * 8 + b] = __fadd_rn(acc[a][b], bin[cg * 8 + b]);
            }
        }
        __syncthreads();
    }
}

// ------------------- fixup B (exact cascade) -------------------
__global__ __launch_bounds__(256, 1) void k_fixB(const float* __restrict__ e0,
                                                 const float* __restrict__ e1,
                                                 const float* __restrict__ e2,
                                                 float* __restrict__ out_idxf) {
    extern __shared__ char sm[];
    float* r8  = (float*)sm;
    float* cbs = (float*)(sm + 8 * 257 * 4);
    float* Ssm = (float*)(sm + 8 * 257 * 4 + 128 * 257 * 4);
    __shared__ float ssr8[8];
    __shared__ int tl[8];
    const int tid = threadIdx.x, warp = tid >> 5, lane = tid & 31;
    const int cnt = g_flagcnt[0];
    if (cnt == 0) return;
    const float* cbl_[3] = {e0, e1, e2};
    const int Kl[3] = {KC0, KC1, KC2};
    const int offl[3] = {0, KC0, KC0 + KC1};

    for (int base = blockIdx.x * 8; base < cnt; base += gridDim.x * 8) {
        if (tid < 8) tl[tid] = g_flaglist[min(base + tid, cnt - 1)];
        __syncthreads();
        for (int i = tid; i < 8 * 256; i += 256)
            r8[(i >> 8) * 257 + (i & 255)] = g_S[(size_t)tl[i >> 8] * P_DIM + (i & 255)];
        __syncthreads();
        if (tid < 8) {
            float s = 0.f;
            for (int p = 0; p < P_DIM; p++)
                s = __fadd_rn(s, __fmul_rn(r8[tid * 257 + p], r8[tid * 257 + p]));
            ssr8[tid] = s;
        }
        __syncthreads();

        int myidx[3];
        double lsd = 0.0;
        for (int lvl = 0; lvl < 3; lvl++) {
            const int K = Kl[lvl];
            const float* cb = cbl_[lvl];
            for (int ch = 0; ch < (K + 127) / 128; ch++) {
                const int rows = min(128, K - ch * 128);
                for (int i = tid; i < rows * 256; i += 256)
                    cbs[(i >> 8) * 257 + (i & 255)] =
                        cb[(size_t)(ch * 128 + (i >> 8)) * P_DIM + (i & 255)];
                __syncthreads();
                for (int m = 0; m < rows / 32; m++) {
                    int jl = m * 32 + lane;
                    float a = 0.f;
                    for (int p = 0; p < P_DIM; p++)
                        a = __fmaf_rn(r8[warp * 257 + p], cbs[jl * 257 + p], a);
                    Ssm[warp * 256 + ch * 128 + jl] = a;
                }
                __syncthreads();
            }
            const float ssr = ssr8[warp];
            float best = CUDART_INF_F;
            int bi = 0x7fffffff;
            for (int kc = 0; kc < K / 32; kc++) {
                int j = kc * 32 + lane;
                float d = __fadd_rn(__fsub_rn(ssr, 2.0f * Ssm[warp * 256 + j]),
                                    g_ssq[offl[lvl] + j]);
                if (d < best) { best = d; bi = j; }
            }
#pragma unroll
            for (int o = 16; o; o >>= 1) {
                float od = __shfl_xor_sync(0xffffffffu, best, o);
                int   oi = __shfl_xor_sync(0xffffffffu, bi, o);
                if (od < best || (od == best && oi < bi)) { best = od; bi = oi; }
            }
            myidx[lvl] = bi;
            const float* er = cb + (size_t)bi * P_DIM;
            double lp = 0.0;
#pragma unroll
            for (int k = 0; k < 8; k++) {
                int p = lane + 32 * k;
                float nv = __fsub_rn(r8[warp * 257 + p], er[p]);
                r8[warp * 257 + p] = nv;
                lp += (double)nv * (double)nv;
            }
#pragma unroll
            for (int o = 16; o; o >>= 1) lp += __shfl_xor_sync(0xffffffffu, lp, o);
            lsd += lp;
            __syncwarp();
            if (lane == 0 && lvl < 2) {
                float s = 0.f;
                for (int p = 0; p < P_DIM; p++)
                    s = __fadd_rn(s, __fmul_rn(r8[warp * 257 + p], r8[warp * 257 + p]));
                ssr8[warp] = s;
            }
            __syncthreads();
        }
        if (lane == 0 && base + warp < cnt) {
            int t = tl[warp];
            g_idx[t] = myidx[0]; g_idx[T_TOK + t] = myidx[1]; g_idx[2 * T_TOK + t] = myidx[2];
            out_idxf[t] = (float)myidx[0];
            out_idxf[T_TOK + t] = (float)myidx[1];
            out_idxf[2 * T_TOK + t] = (float)myidx[2];
            g_losstok[t] = (float)lsd;
        }
        __syncthreads();
    }
}

// ------------------- loss reduce -------------------
__global__ __launch_bounds__(256) void k_lossred(float* __restrict__ out_loss) {
    __shared__ double smm[256];
    double s = 0.0;
    for (int i = threadIdx.x; i < T_TOK; i += 256) s += (double)g_losstok[i];
    smm[threadIdx.x] = s;
    __syncthreads();
    for (int o = 128; o; o >>= 1) {
        if (threadIdx.x < o) smm[threadIdx.x] += smm[threadIdx.x + o];
        __syncthreads();
    }
    if (threadIdx.x == 0)
        *out_loss = (float)(smm[0] * (0.25 / (3.0 * (double)T_TOK * (double)P_DIM)));
}

// ------------------- EW = emb_cat @ W_out -------------------
__global__ __launch_bounds__(256) void k_ew(const float* __restrict__ e0,
                                            const float* __restrict__ e1,
                                            const float* __restrict__ e2,
                                            const float* __restrict__ Wout) {
    __shared__ float a[8][P_DIM];
    const int rbase = blockIdx.x * 8;
    for (int i = threadIdx.x; i < 8 * P_DIM; i += 256) {
        int r = rbase + i / P_DIM, p = i % P_DIM;
        const float* s = (r < KC0) ? (e0 + (size_t)r * P_DIM)
                       : (r < KC0 + KC1) ? (e1 + (size_t)(r - KC0) * P_DIM)
                                         : (e2 + (size_t)(r - KC0 - KC1) * P_DIM);
        a[i / P_DIM][p] = s[p];
    }
    __syncthreads();
    for (int c = threadIdx.x; c < D_DIM; c += 256) {
        float acc[8] = {0.f, 0.f, 0.f, 0.f, 0.f, 0.f, 0.f, 0.f};
        for (int p = 0; p < P_DIM; p++) {
            float w = Wout[(size_t)p * D_DIM + c];
#pragma unroll
            for (int r = 0; r < 8; r++) acc[r] = __fmaf_rn(a[r][p], w, acc[r]);
        }
#pragma unroll
        for (int r = 0; r < 8; r++) g_EW[(size_t)(rbase + r) * D_DIM + c] = acc[r];
    }
}

// ------------------- output gather -------------------
__global__ __launch_bounds__(352) void k_out(const float* __restrict__ bout,
                                             float* __restrict__ out) {
    const int t = blockIdx.x;
    const int i0 = g_idx[t], i1 = g_idx[T_TOK + t], i2 = g_idx[2 * T_TOK + t];
    const float4* r0 = (const float4*)(g_EW + (size_t)i0 * D_DIM);
    const float4* r1 = (const float4*)(g_EW + (size_t)(KC0 + i1) * D_DIM);
    const float4* r2 = (const float4*)(g_EW + (size_t)(KC0 + KC1 + i2) * D_DIM);
    const float4* bb = (const float4*)bout;
    float4* o = (float4*)(out + (size_t)t * D_DIM);
    const int c = threadIdx.x;
    float4 a = r0[c], b = r1[c], cc = r2[c], d = bb[c];
    o[c] = make_float4(a.x + b.x + cc.x + d.x, a.y + b.y + cc.y + d.y,
                       a.z + b.z + cc.z + d.z, a.w + b.w + cc.w + d.w);
}

// ------------------- launch -------------------
extern "C" void kernel_launch(void* const* d_in, const int* in_sizes, int n_in,
                              void* d_out, int out_size) {
    const float* z     = (const float*)d_in[0];
    const float* W_in  = (const float*)d_in[1];
    const float* b_in  = (const float*)d_in[2];
    const float* W_out = (const float*)d_in[3];
    const float* b_out = (const float*)d_in[4];
    const float* e0    = (const float*)d_in[5];
    const float* e1    = (const float*)d_in[6];
    const float* e2    = (const float*)d_in[7];

    float* out      = (float*)d_out;
    float* out_idxf = out + (size_t)T_TOK * D_DIM;
    float* out_loss = out_idxf + 3 * T_TOK;

    cudaFuncSetAttribute(k_fixA, cudaFuncAttributeMaxDynamicSharedMemorySize,
                         32 * 68 * 4 + 64 * 256 * 4);
    cudaFuncSetAttribute(k_fixB, cudaFuncAttributeMaxDynamicSharedMemorySize,
                         8 * 257 * 4 + 128 * 257 * 4 + 8 * 256 * 4);

    k_zero1<<<1, 32>>>();
    k_zprep<<<(int)(((size_t)T_TOK * D_DIM) / (256 * 8)), 256>>>(z);
    k_wprep<<<dim3(D_DIM / 32, P_DIM / 32), 256>>>(W_in);
    k_cbprep<<<KT, 256>>>(e0, e1, e2);
    k_ssqE<<<(KT + 7) / 8, 256>>>(e0, e1, e2);
    k_tables<<<7168, 256>>>(e0, e1, e2);
    k_ew<<<KT / 8, 256>>>(e0, e1, e2, W_out);

    k_gemm1_mma<<<dim3(2, T_TOK / 128), 256>>>(b_in);
    k_ssr<<<T_TOK / 8, 256>>>();
    k_gemmS_mma<<<dim3(KT / 64, T_TOK / 128), 256>>>();
    k_pickcas<<<T_TOK / 8, 256>>>(out_idxf);

    k_compact<<<64, 256>>>();
    k_fixA<<<256, 256, 32 * 68 * 4 + 64 * 256 * 4>>>(z, W_in, b_in);
    k_fixB<<<512, 256, 8 * 257 * 4 + 128 * 257 * 4 + 8 * 256 * 4>>>(e0, e1, e2, out_idxf);

    k_lossred<<<1, 256>>>(out_loss);
    k_out<<<T_TOK, 352>>>(b_out, out);
}

// round 11
// speedup vs baseline: 1.2488x; 1.0689x over previous
#include <cuda_runtime.h>
#include <cuda_fp16.h>
#include <math_constants.h>
#include <cstdint>

#define T_TOK 32768
#define D_DIM 1408
#define P_DIM 256
#define KC0 64
#define KC1 128
#define KC2 256
#define KT  448
#define TAU 1e-2f

// ------------------- device scratch -------------------
static __device__ float  g_r[(size_t)T_TOK * P_DIM];      // approx zproj fp32 (for ssr)
static __device__ float  g_S[(size_t)T_TOK * KT];         // scores; reused as exact-zproj store
static __device__ float  g_ssq[KT];
static __device__ float  g_ssr[T_TOK];
static __device__ float  g_G01[KC0 * KC1];
static __device__ float  g_G02[KC0 * KC2];
static __device__ float  g_G12[KC1 * KC2];
static __device__ float  g_EW[(size_t)KT * D_DIM];
static __device__ int    g_idx[3 * T_TOK];
static __device__ float  g_losstok[T_TOK];
static __device__ int    g_flagged[T_TOK];
static __device__ int    g_flagcnt[1];
static __device__ int    g_flaglist[T_TOK];
static __device__ __half g_WhT[(size_t)P_DIM * D_DIM];    // W_in^T fp16 [256][1408]
static __device__ __half g_zh[(size_t)T_TOK * D_DIM];     // z fp16
static __device__ __half g_rh[(size_t)T_TOK * P_DIM];     // zproj fp16
static __device__ __half g_cbh[KT * P_DIM];               // codebooks fp16 [448][256]

// ------------------- helpers -------------------
__device__ __forceinline__ uint32_t smem_u32(const void* p) {
    uint32_t a;
    asm("{ .reg .u64 t; cvta.to.shared.u64 t, %1; cvt.u32.u64 %0, t; }" : "=r"(a) : "l"(p));
    return a;
}
__device__ __forceinline__ void ldm4(uint32_t r[4], uint32_t a) {
    asm volatile("ldmatrix.sync.aligned.m8n8.x4.shared.b16 {%0,%1,%2,%3}, [%4];"
                 : "=r"(r[0]), "=r"(r[1]), "=r"(r[2]), "=r"(r[3]) : "r"(a));
}
__device__ __forceinline__ void mma_fp16(float c[4], const uint32_t a[4], const uint32_t b[2]) {
    asm volatile("mma.sync.aligned.m16n8k16.row.col.f32.f16.f16.f32 "
                 "{%0,%1,%2,%3}, {%4,%5,%6,%7}, {%8,%9}, {%0,%1,%2,%3};"
                 : "+f"(c[0]), "+f"(c[1]), "+f"(c[2]), "+f"(c[3])
                 : "r"(a[0]), "r"(a[1]), "r"(a[2]), "r"(a[3]), "r"(b[0]), "r"(b[1]));
}

// ------------------- zero counter -------------------
__global__ void k_zero1() { if (threadIdx.x == 0) g_flagcnt[0] = 0; }

// ------------------- z -> fp16 -------------------
__global__ __launch_bounds__(256) void k_zprep(const float* __restrict__ z) {
    const size_t base = ((size_t)blockIdx.x * 256 + threadIdx.x) * 8;
    float4 v0 = *(const float4*)(z + base);
    float4 v1 = *(const float4*)(z + base + 4);
    __half2 p0 = __floats2half2_rn(v0.x, v0.y);
    __half2 p1 = __floats2half2_rn(v0.z, v0.w);
    __half2 p2 = __floats2half2_rn(v1.x, v1.y);
    __half2 p3 = __floats2half2_rn(v1.z, v1.w);
    *(uint4*)(g_zh + base) = make_uint4(*(uint32_t*)&p0, *(uint32_t*)&p1,
                                        *(uint32_t*)&p2, *(uint32_t*)&p3);
}

// ------------------- W_in -> fp16 transpose -------------------
__global__ __launch_bounds__(256) void k_wprep(const float* __restrict__ Win) {
    __shared__ float tile[32][33];
    const int r0 = blockIdx.x * 32, c0 = blockIdx.y * 32;
    const int tx = threadIdx.x & 31, ty = threadIdx.x >> 5;
    for (int rr = ty; rr < 32; rr += 8)
        tile[rr][tx] = Win[(size_t)(r0 + rr) * P_DIM + c0 + tx];
    __syncthreads();
    for (int rr = ty; rr < 32; rr += 8)
        g_WhT[(size_t)(c0 + rr) * D_DIM + r0 + tx] = __float2half_rn(tile[tx][rr]);
}

// ------------------- codebooks -> fp16 -------------------
__global__ __launch_bounds__(256) void k_cbprep(const float* __restrict__ e0,
                                                const float* __restrict__ e1,
                                                const float* __restrict__ e2) {
    const int row = blockIdx.x;
    const float* src = (row < KC0) ? (e0 + (size_t)row * P_DIM)
                     : (row < KC0 + KC1) ? (e1 + (size_t)(row - KC0) * P_DIM)
                                         : (e2 + (size_t)(row - KC0 - KC1) * P_DIM);
    g_cbh[row * P_DIM + threadIdx.x] = __float2half_rn(src[threadIdx.x]);
}

// ------------------- ssq (exact fp32 sequential order) -------------------
__global__ __launch_bounds__(256) void k_ssqE(const float* __restrict__ e0,
                                              const float* __restrict__ e1,
                                              const float* __restrict__ e2) {
    __shared__ float buf[8][260];
    const int warp = threadIdx.x >> 5, lane = threadIdx.x & 31;
    const int r = blockIdx.x * 8 + warp;
    if (r >= KT) return;
    const float* src = (r < KC0) ? (e0 + (size_t)r * P_DIM)
                     : (r < KC0 + KC1) ? (e1 + (size_t)(r - KC0) * P_DIM)
                                       : (e2 + (size_t)(r - KC0 - KC1) * P_DIM);
#pragma unroll
    for (int k = 0; k < 8; k++) buf[warp][lane + 32 * k] = src[lane + 32 * k];
    __syncwarp();
    if (lane == 0) {
        float s = 0.f;
        for (int p = 0; p < P_DIM; p++) s = __fadd_rn(s, __fmul_rn(buf[warp][p], buf[warp][p]));
        g_ssq[r] = s;
    }
}

// ------------------- Gram tables -------------------
__global__ __launch_bounds__(256) void k_tables(const float* __restrict__ e0,
                                                const float* __restrict__ e1,
                                                const float* __restrict__ e2) {
    int gw = (blockIdx.x * 256 + threadIdx.x) >> 5;
    int lane = threadIdx.x & 31;
    if (gw >= 57344) return;
    const float *a, *b;
    float* dst;
    if (gw < 8192) {
        a = e0 + (size_t)(gw >> 7) * P_DIM;
        b = e1 + (size_t)(gw & 127) * P_DIM;
        dst = g_G01 + gw;
    } else if (gw < 24576) {
        int id = gw - 8192;
        a = e0 + (size_t)(id >> 8) * P_DIM;
        b = e2 + (size_t)(id & 255) * P_DIM;
        dst = g_G02 + id;
    } else {
        int id = gw - 24576;
        a = e1 + (size_t)(id >> 8) * P_DIM;
        b = e2 + (size_t)(id & 255) * P_DIM;
        dst = g_G12 + id;
    }
    float s = 0.f;
#pragma unroll
    for (int k = 0; k < 8; k++) s += a[lane + 32 * k] * b[lane + 32 * k];
#pragma unroll
    for (int o = 16; o; o >>= 1) s += __shfl_xor_sync(0xffffffffu, s, o);
    if (lane == 0) *dst = s;
}

// ------------------- GEMM1: fp16 single-product, reg-staged pipeline -----------------
__global__ __launch_bounds__(256) void k_gemm1_mma(const float* __restrict__ bin) {
    __shared__ __half Ah[128][40], Bh[128][40];
    const int tid = threadIdx.x, wid = tid >> 5, lane = tid & 31;
    const int warp_m = wid >> 2, warp_n = wid & 3;
    const size_t bm = (size_t)blockIdx.y * 128;
    const int bnG = blockIdx.x * 128;
    const uint32_t sAh = smem_u32(Ah), sBh = smem_u32(Bh);
    const int g = lane >> 3, lr = lane & 7;
    const int l_r0 = (tid * 2) >> 2, l_c0 = (tid * 2) & 3;
    const int l_r1 = (tid * 2 + 1) >> 2, l_c1 = (tid * 2 + 1) & 3;

    float acc[4][4][4];
#pragma unroll
    for (int mt = 0; mt < 4; mt++)
#pragma unroll
        for (int nt = 0; nt < 4; nt++)
#pragma unroll
            for (int q = 0; q < 4; q++) acc[mt][nt][q] = 0.f;

    uint4 rA[2], rB[2];
    auto load_tile = [&](int kc) {
        const int k0 = kc * 32;
        rA[0] = *(const uint4*)(g_zh + (bm + l_r0) * D_DIM + k0 + l_c0 * 8);
        rA[1] = *(const uint4*)(g_zh + (bm + l_r1) * D_DIM + k0 + l_c1 * 8);
        rB[0] = *(const uint4*)(g_WhT + (size_t)(bnG + l_r0) * D_DIM + k0 + l_c0 * 8);
        rB[1] = *(const uint4*)(g_WhT + (size_t)(bnG + l_r1) * D_DIM + k0 + l_c1 * 8);
    };
    auto store_tile = [&]() {
        *(uint4*)&Ah[l_r0][l_c0 * 8] = rA[0];
        *(uint4*)&Ah[l_r1][l_c1 * 8] = rA[1];
        *(uint4*)&Bh[l_r0][l_c0 * 8] = rB[0];
        *(uint4*)&Bh[l_r1][l_c1 * 8] = rB[1];
    };

    load_tile(0);
    for (int kc = 0; kc < D_DIM / 32; kc++) {
        store_tile();
        __syncthreads();
        if (kc + 1 < D_DIM / 32) load_tile(kc + 1);
#pragma unroll
        for (int ks = 0; ks < 2; ks++) {
            const int kk = ks * 16;
            uint32_t bf[4][2];
#pragma unroll
            for (int p = 0; p < 2; p++) {
                const int n0 = warp_n * 32 + p * 16;
                uint32_t off = (uint32_t)((n0 + ((g >> 1) << 3) + lr) * 40 + kk + ((g & 1) << 3)) * 2;
                uint32_t t[4];
                ldm4(t, sBh + off);
                bf[p * 2][0] = t[0]; bf[p * 2][1] = t[1];
                bf[p * 2 + 1][0] = t[2]; bf[p * 2 + 1][1] = t[3];
            }
#pragma unroll
            for (int mt = 0; mt < 4; mt++) {
                const int m0 = warp_m * 64 + mt * 16;
                uint32_t aoff = (uint32_t)((m0 + ((g & 1) << 3) + lr) * 40 + kk + ((g >> 1) << 3)) * 2;
                uint32_t ah[4];
                ldm4(ah, sAh + aoff);
#pragma unroll
                for (int nt = 0; nt < 4; nt++) mma_fp16(acc[mt][nt], ah, bf[nt]);
            }
        }
        __syncthreads();
    }
    // epilogue: + bias -> g_r fp32 and g_rh fp16
#pragma unroll
    for (int mt = 0; mt < 4; mt++) {
        const size_t row = bm + warp_m * 64 + mt * 16 + (lane >> 2);
#pragma unroll
        for (int nt = 0; nt < 4; nt++) {
            const int col = bnG + warp_n * 32 + nt * 8 + ((lane & 3) << 1);
            float b0 = bin[col], b1 = bin[col + 1];
            float v0 = acc[mt][nt][0] + b0, v1 = acc[mt][nt][1] + b1;
            float v2 = acc[mt][nt][2] + b0, v3 = acc[mt][nt][3] + b1;
            *(float2*)(g_r + row * P_DIM + col) = make_float2(v0, v1);
            *(float2*)(g_r + (row + 8) * P_DIM + col) = make_float2(v2, v3);
            __half2 p = __floats2half2_rn(v0, v1);
            *(uint32_t*)(g_rh + row * P_DIM + col) = *(uint32_t*)&p;
            p = __floats2half2_rn(v2, v3);
            *(uint32_t*)(g_rh + (row + 8) * P_DIM + col) = *(uint32_t*)&p;
        }
    }
}

// ------------------- GEMMS: fp16 single-product -------------------
__global__ __launch_bounds__(256) void k_gemmS_mma() {
    __shared__ __half Ah[128][40], Bh[64][40];
    const int tid = threadIdx.x, wid = tid >> 5, lane = tid & 31;
    const int warp_m = wid >> 1, warp_n = wid & 1;
    const size_t bm = (size_t)blockIdx.y * 128;
    const int bn = blockIdx.x * 64;
    const uint32_t sAh = smem_u32(Ah), sBh = smem_u32(Bh);
    const int g = lane >> 3, lr = lane & 7;
    const int a_r0 = (tid * 2) >> 2, a_c0 = (tid * 2) & 3;
    const int a_r1 = (tid * 2 + 1) >> 2, a_c1 = (tid * 2 + 1) & 3;
    const int b_r = tid >> 2, b_c = tid & 3;

    float acc[2][4][4];
#pragma unroll
    for (int mt = 0; mt < 2; mt++)
#pragma unroll
        for (int nt = 0; nt < 4; nt++)
#pragma unroll
            for (int q = 0; q < 4; q++) acc[mt][nt][q] = 0.f;

    uint4 rA[2], rB;
    auto load_tile = [&](int kc) {
        const int k0 = kc * 32;
        rA[0] = *(const uint4*)(g_rh + (bm + a_r0) * P_DIM + k0 + a_c0 * 8);
        rA[1] = *(const uint4*)(g_rh + (bm + a_r1) * P_DIM + k0 + a_c1 * 8);
        rB = *(const uint4*)(g_cbh + (size_t)(bn + b_r) * P_DIM + k0 + b_c * 8);
    };
    auto store_tile = [&]() {
        *(uint4*)&Ah[a_r0][a_c0 * 8] = rA[0];
        *(uint4*)&Ah[a_r1][a_c1 * 8] = rA[1];
        *(uint4*)&Bh[b_r][b_c * 8] = rB;
    };

    load_tile(0);
    for (int kc = 0; kc < P_DIM / 32; kc++) {
        store_tile();
        __syncthreads();
        if (kc + 1 < P_DIM / 32) load_tile(kc + 1);
#pragma unroll
        for (int ks = 0; ks < 2; ks++) {
            const int kk = ks * 16;
            uint32_t bf[4][2];
#pragma unroll
            for (int p = 0; p < 2; p++) {
                const int n0 = warp_n * 32 + p * 16;
                uint32_t off = (uint32_t)((n0 + ((g >> 1) << 3) + lr) * 40 + kk + ((g & 1) << 3)) * 2;
                uint32_t t[4];
                ldm4(t, sBh + off);
                bf[p * 2][0] = t[0]; bf[p * 2][1] = t[1];
                bf[p * 2 + 1][0] = t[2]; bf[p * 2 + 1][1] = t[3];
            }
#pragma unroll
            for (int mt = 0; mt < 2; mt++) {
                const int m0 = warp_m * 32 + mt * 16;
                uint32_t aoff = (uint32_t)((m0 + ((g & 1) << 3) + lr) * 40 + kk + ((g >> 1) << 3)) * 2;
                uint32_t ah[4];
                ldm4(ah, sAh + aoff);
#pragma unroll
                for (int nt = 0; nt < 4; nt++) mma_fp16(acc[mt][nt], ah, bf[nt]);
            }
        }
        __syncthreads();
    }
#pragma unroll
    for (int mt = 0; mt < 2; mt++) {
        const size_t row = bm + warp_m * 32 + mt * 16 + (lane >> 2);
#pragma unroll
        for (int nt = 0; nt < 4; nt++) {
            const int col = bn + warp_n * 32 + nt * 8 + ((lane & 3) << 1);
            *(float2*)(g_S + row * KT + col) = make_float2(acc[mt][nt][0], acc[mt][nt][1]);
            *(float2*)(g_S + (row + 8) * KT + col) = make_float2(acc[mt][nt][2], acc[mt][nt][3]);
        }
    }
}

// ------------------- ssr -------------------
__global__ __launch_bounds__(256) void k_ssr() {
    const int warp = threadIdx.x >> 5, lane = threadIdx.x & 31;
    const size_t t = (size_t)blockIdx.x * 8 + warp;
    const float* rr = g_r + t * P_DIM;
    float s = 0.f;
#pragma unroll
    for (int k = 0; k < 8; k++) { float v = rr[lane + 32 * k]; s += v * v; }
#pragma unroll
    for (int o = 16; o; o >>= 1) s += __shfl_xor_sync(0xffffffffu, s, o);
    if (lane == 0) g_ssr[t] = s;
}

// ------------------- cascade pick -------------------
__device__ __forceinline__ void top2_reduce(float& m1, float& m2, int& i1) {
#pragma unroll
    for (int o = 16; o; o >>= 1) {
        float om1 = __shfl_xor_sync(0xffffffffu, m1, o);
        int   oi1 = __shfl_xor_sync(0xffffffffu, i1, o);
        float om2 = __shfl_xor_sync(0xffffffffu, m2, o);
        if (om1 < m1 || (om1 == m1 && oi1 < i1)) { m2 = fminf(m1, om2); m1 = om1; i1 = oi1; }
        else m2 = fminf(m2, om1);
    }
}

__global__ __launch_bounds__(256) void k_pickcas(float* __restrict__ out_idxf) {
    __shared__ float ssq_s[KT];
    for (int i = threadIdx.x; i < KT; i += 256) ssq_s[i] = g_ssq[i];
    __syncthreads();
    const int warp = threadIdx.x >> 5, lane = threadIdx.x & 31;
    const int t = blockIdx.x * 8 + warp;
    const float* Srow = g_S + (size_t)t * KT;

    float m1 = CUDART_INF_F, m2 = CUDART_INF_F; int i1 = 0x7fffffff;
#pragma unroll
    for (int kc = 0; kc < 2; kc++) {
        int j = kc * 32 + lane;
        float d = ssq_s[j] - 2.0f * Srow[j];
        if (d < m1) { m2 = m1; m1 = d; i1 = j; } else m2 = fminf(m2, d);
    }
    top2_reduce(m1, m2, i1);
    const int i0 = i1; const float mv0 = m1, gap0 = m2 - m1;

    const float* g01 = g_G01 + i0 * KC1;
    m1 = CUDART_INF_F; m2 = CUDART_INF_F; i1 = 0x7fffffff;
#pragma unroll
    for (int kc = 0; kc < 4; kc++) {
        int j = kc * 32 + lane;
        float d = ssq_s[KC0 + j] - 2.0f * (Srow[KC0 + j] - g01[j]);
        if (d < m1) { m2 = m1; m1 = d; i1 = j; } else m2 = fminf(m2, d);
    }
    top2_reduce(m1, m2, i1);
    const int idx1 = i1; const float mv1 = m1, gap1 = m2 - m1;

    const float* g02 = g_G02 + i0 * KC2;
    const float* g12 = g_G12 + idx1 * KC2;
    m1 = CUDART_INF_F; m2 = CUDART_INF_F; i1 = 0x7fffffff;
#pragma unroll
    for (int kc = 0; kc < 8; kc++) {
        int j = kc * 32 + lane;
        float d = ssq_s[KC0 + KC1 + j] - 2.0f * (Srow[KC0 + KC1 + j] - g02[j] - g12[j]);
        if (d < m1) { m2 = m1; m1 = d; i1 = j; } else m2 = fminf(m2, d);
    }
    top2_reduce(m1, m2, i1);
    const int idx2 = i1; const float mv2 = m1, gap2 = m2 - m1;

    if (lane == 0) {
        g_idx[t] = i0; g_idx[T_TOK + t] = idx1; g_idx[2 * T_TOK + t] = idx2;
        out_idxf[t] = (float)i0;
        out_idxf[T_TOK + t] = (float)idx1;
        out_idxf[2 * T_TOK + t] = (float)idx2;
        g_flagged[t] = (gap0 < TAU || gap1 < TAU || gap2 < TAU) ? 1 : 0;
        float s = g_ssr[t];
        g_losstok[t] = 3.f * s + 3.f * mv0 + 2.f * mv1 + mv2;
    }
}

// ------------------- compact -------------------
__global__ __launch_bounds__(256) void k_compact() {
    int i = blockIdx.x * 256 + threadIdx.x;
    for (; i < T_TOK; i += gridDim.x * 256)
        if (g_flagged[i]) g_flaglist[atomicAdd(&g_flagcnt[0], 1)] = i;
}

// ------------------- fixup A (exact zproj) -------------------
__global__ __launch_bounds__(256) void k_fixA(const float* __restrict__ z,
                                              const float* __restrict__ Win,
                                              const float* __restrict__ bin) {
    extern __shared__ char sm[];
    float* zsm = (float*)sm;
    float* Wsm = (float*)(sm + 32 * 68 * 4);
    __shared__ int tl[32];
    const int tid = threadIdx.x;
    const int cnt = g_flagcnt[0];
    if (cnt == 0) return;

    for (int base = blockIdx.x * 32; base < cnt; base += gridDim.x * 32) {
        if (tid < 32) tl[tid] = g_flaglist[min(base + tid, cnt - 1)];
        __syncthreads();
        const int tg = tid >> 5, cg = tid & 31;
        float acc[4][8];
#pragma unroll
        for (int a = 0; a < 4; a++)
#pragma unroll
            for (int b = 0; b < 8; b++) acc[a][b] = 0.f;

        for (int kc = 0; kc < D_DIM / 64; kc++) {
#pragma unroll
            for (int q = 0; q < 2; q++) {
                int i = tid + q * 256;
                int s = i >> 4, c4 = i & 15;
                *(float4*)(zsm + s * 68 + c4 * 4) =
                    *(const float4*)(z + (size_t)tl[s] * D_DIM + kc * 64 + c4 * 4);
            }
#pragma unroll
            for (int q = 0; q < 16; q++) {
                int i = tid + q * 256;
                int k = i >> 6, c4 = i & 63;
                *(float4*)(Wsm + k * 256 + c4 * 4) =
                    *(const float4*)(Win + (size_t)(kc * 64 + k) * P_DIM + c4 * 4);
            }
            __syncthreads();
            for (int k = 0; k < 64; k++) {
                float4 w0 = *(const float4*)(Wsm + k * 256 + cg * 8);
                float4 w1 = *(const float4*)(Wsm + k * 256 + cg * 8 + 4);
                float wv[8] = {w0.x, w0.y, w0.z, w0.w, w1.x, w1.y, w1.z, w1.w};
#pragma unroll
                for (int a = 0; a < 4; a++) {
                    float zv = zsm[(tg * 4 + a) * 68 + k];
#pragma unroll
                    for (int b = 0; b < 8; b++)
                        acc[a][b] = __fmaf_rn(zv, wv[b], acc[a][b]);
                }
            }
            __syncthreads();
        }
#pragma unroll
        for (int a = 0; a < 4; a++) {
            int s = tg * 4 + a;
            if (base + s < cnt) {
                float* dst = g_S + (size_t)tl[s] * P_DIM;
#pragma unroll
                for (int b = 0; b < 8; b++)
                    dst[cg * 8 + b] = __fadd_rn(acc[a][b], bin[cg * 8 + b]);
            }
        }
        __syncthreads();
    }
}

// ------------------- fixup B (exact cascade, Round-3 arithmetic) ---------------------
__global__ __launch_bounds__(256) void k_fixB(const float* __restrict__ e0,
                                              const float* __restrict__ e1,
                                              const float* __restrict__ e2,
                                              float* __restrict__ out_idxf) {
    extern __shared__ char sm[];
    float* r8  = (float*)sm;
    float* cbs = (float*)(sm + 8 * 257 * 4);
    float* Ssm = (float*)(sm + 8 * 257 * 4 + 128 * 257 * 4);
    __shared__ float ssr8[8];
    __shared__ int tl[8];
    const int tid = threadIdx.x, warp = tid >> 5, lane = tid & 31;
    const int cnt = g_flagcnt[0];
    if (cnt == 0) return;
    const float* cbl_[3] = {e0, e1, e2};
    const int Kl[3] = {KC0, KC1, KC2};
    const int offl[3] = {0, KC0, KC0 + KC1};

    for (int base = blockIdx.x * 8; base < cnt; base += gridDim.x * 8) {
        if (tid < 8) tl[tid] = g_flaglist[min(base + tid, cnt - 1)];
        __syncthreads();
        for (int i = tid; i < 8 * 256; i += 256)
            r8[(i >> 8) * 257 + (i & 255)] = g_S[(size_t)tl[i >> 8] * P_DIM + (i & 255)];
        __syncthreads();
        if (tid < 8) {
            float s = 0.f;
            for (int p = 0; p < P_DIM; p++)
                s = __fadd_rn(s, __fmul_rn(r8[tid * 257 + p], r8[tid * 257 + p]));
            ssr8[tid] = s;
        }
        __syncthreads();

        int myidx[3];
        double lsd = 0.0;
        for (int lvl = 0; lvl < 3; lvl++) {
            const int K = Kl[lvl];
            const float* cb = cbl_[lvl];
            for (int ch = 0; ch < (K + 127) / 128; ch++) {
                const int rows = min(128, K - ch * 128);
                for (int i = tid; i < rows * 256; i += 256)
                    cbs[(i >> 8) * 257 + (i & 255)] =
                        cb[(size_t)(ch * 128 + (i >> 8)) * P_DIM + (i & 255)];
                __syncthreads();
                for (int m = 0; m < rows / 32; m++) {
                    int jl = m * 32 + lane;
                    float a = 0.f;
                    for (int p = 0; p < P_DIM; p++)
                        a = __fmaf_rn(r8[warp * 257 + p], cbs[jl * 257 + p], a);
                    Ssm[warp * 256 + ch * 128 + jl] = a;
                }
                __syncthreads();
            }
            const float ssr = ssr8[warp];
            float best = CUDART_INF_F;
            int bi = 0x7fffffff;
            for (int kc = 0; kc < K / 32; kc++) {
                int j = kc * 32 + lane;
                float d = __fadd_rn(__fsub_rn(ssr, 2.0f * Ssm[warp * 256 + j]),
                                    g_ssq[offl[lvl] + j]);
                if (d < best) { best = d; bi = j; }
            }
#pragma unroll
            for (int o = 16; o; o >>= 1) {
                float od = __shfl_xor_sync(0xffffffffu, best, o);
                int   oi = __shfl_xor_sync(0xffffffffu, bi, o);
                if (od < best || (od == best && oi < bi)) { best = od; bi = oi; }
            }
            myidx[lvl] = bi;
            const float* er = cb + (size_t)bi * P_DIM;
            double lp = 0.0;
#pragma unroll
            for (int k = 0; k < 8; k++) {
                int p = lane + 32 * k;
                float nv = __fsub_rn(r8[warp * 257 + p], er[p]);
                r8[warp * 257 + p] = nv;
                lp += (double)nv * (double)nv;
            }
#pragma unroll
            for (int o = 16; o; o >>= 1) lp += __shfl_xor_sync(0xffffffffu, lp, o);
            lsd += lp;
            __syncwarp();
            if (lane == 0 && lvl < 2) {
                float s = 0.f;
                for (int p = 0; p < P_DIM; p++)
                    s = __fadd_rn(s, __fmul_rn(r8[warp * 257 + p], r8[warp * 257 + p]));
                ssr8[warp] = s;
            }
            __syncthreads();
        }
        if (lane == 0 && base + warp < cnt) {
            int t = tl[warp];
            g_idx[t] = myidx[0]; g_idx[T_TOK + t] = myidx[1]; g_idx[2 * T_TOK + t] = myidx[2];
            out_idxf[t] = (float)myidx[0];
            out_idxf[T_TOK + t] = (float)myidx[1];
            out_idxf[2 * T_TOK + t] = (float)myidx[2];
            g_losstok[t] = (float)lsd;
        }
        __syncthreads();
    }
}

// ------------------- loss reduce -------------------
__global__ __launch_bounds__(256) void k_lossred(float* __restrict__ out_loss) {
    __shared__ double smm[256];
    double s = 0.0;
    for (int i = threadIdx.x; i < T_TOK; i += 256) s += (double)g_losstok[i];
    smm[threadIdx.x] = s;
    __syncthreads();
    for (int o = 128; o; o >>= 1) {
        if (threadIdx.x < o) smm[threadIdx.x] += smm[threadIdx.x + o];
        __syncthreads();
    }
    if (threadIdx.x == 0)
        *out_loss = (float)(smm[0] * (0.25 / (3.0 * (double)T_TOK * (double)P_DIM)));
}

// ------------------- EW = emb_cat @ W_out -------------------
__global__ __launch_bounds__(256) void k_ew(const float* __restrict__ e0,
                                            const float* __restrict__ e1,
                                            const float* __restrict__ e2,
                                            const float* __restrict__ Wout) {
    __shared__ float a[8][P_DIM];
    const int rbase = blockIdx.x * 8;
    for (int i = threadIdx.x; i < 8 * P_DIM; i += 256) {
        int r = rbase + i / P_DIM, p = i % P_DIM;
        const float* s = (r < KC0) ? (e0 + (size_t)r * P_DIM)
                       : (r < KC0 + KC1) ? (e1 + (size_t)(r - KC0) * P_DIM)
                                         : (e2 + (size_t)(r - KC0 - KC1) * P_DIM);
        a[i / P_DIM][p] = s[p];
    }
    __syncthreads();
    for (int c = threadIdx.x; c < D_DIM; c += 256) {
        float acc[8] = {0.f, 0.f, 0.f, 0.f, 0.f, 0.f, 0.f, 0.f};
        for (int p = 0; p < P_DIM; p++) {
            float w = Wout[(size_t)p * D_DIM + c];
#pragma unroll
            for (int r = 0; r < 8; r++) acc[r] = __fmaf_rn(a[r][p], w, acc[r]);
        }
#pragma unroll
        for (int r = 0; r < 8; r++) g_EW[(size_t)(rbase + r) * D_DIM + c] = acc[r];
    }
}

// ------------------- output gather -------------------
__global__ __launch_bounds__(352) void k_out(const float* __restrict__ bout,
                                             float* __restrict__ out) {
    const int t = blockIdx.x;
    const int i0 = g_idx[t], i1 = g_idx[T_TOK + t], i2 = g_idx[2 * T_TOK + t];
    const float4* r0 = (const float4*)(g_EW + (size_t)i0 * D_DIM);
    const float4* r1 = (const float4*)(g_EW + (size_t)(KC0 + i1) * D_DIM);
    const float4* r2 = (const float4*)(g_EW + (size_t)(KC0 + KC1 + i2) * D_DIM);
    const float4* bb = (const float4*)bout;
    float4* o = (float4*)(out + (size_t)t * D_DIM);
    const int c = threadIdx.x;
    float4 a = r0[c], b = r1[c], cc = r2[c], d = bb[c];
    o[c] = make_float4(a.x + b.x + cc.x + d.x, a.y + b.y + cc.y + d.y,
                       a.z + b.z + cc.z + d.z, a.w + b.w + cc.w + d.w);
}

// ------------------- launch -------------------
extern "C" void kernel_launch(void* const* d_in, const int* in_sizes, int n_in,
                              void* d_out, int out_size) {
    const float* z     = (const float*)d_in[0];
    const float* W_in  = (const float*)d_in[1];
    const float* b_in  = (const float*)d_in[2];
    const float* W_out = (const float*)d_in[3];
    const float* b_out = (const float*)d_in[4];
    const float* e0    = (const float*)d_in[5];
    const float* e1    = (const float*)d_in[6];
    const float* e2    = (const float*)d_in[7];

    float* out      = (float*)d_out;
    float* out_idxf = out + (size_t)T_TOK * D_DIM;
    float* out_loss = out_idxf + 3 * T_TOK;

    cudaFuncSetAttribute(k_fixA, cudaFuncAttributeMaxDynamicSharedMemorySize,
                         32 * 68 * 4 + 64 * 256 * 4);
    cudaFuncSetAttribute(k_fixB, cudaFuncAttributeMaxDynamicSharedMemorySize,
                         8 * 257 * 4 + 128 * 257 * 4 + 8 * 256 * 4);

    k_zero1<<<1, 32>>>();
    k_zprep<<<(int)(((size_t)T_TOK * D_DIM) / (256 * 8)), 256>>>(z);
    k_wprep<<<dim3(D_DIM / 32, P_DIM / 32), 256>>>(W_in);
    k_cbprep<<<KT, 256>>>(e0, e1, e2);
    k_ssqE<<<(KT + 7) / 8, 256>>>(e0, e1, e2);
    k_tables<<<7168, 256>>>(e0, e1, e2);
    k_ew<<<KT / 8, 256>>>(e0, e1, e2, W_out);

    k_gemm1_mma<<<dim3(2, T_TOK / 128), 256>>>(b_in);
    k_ssr<<<T_TOK / 8, 256>>>();
    k_gemmS_mma<<<dim3(KT / 64, T_TOK / 128), 256>>>();
    k_pickcas<<<T_TOK / 8, 256>>>(out_idxf);

    k_compact<<<64, 256>>>();
    k_fixA<<<256, 256, 32 * 68 * 4 + 64 * 256 * 4>>>(z, W_in, b_in);
    k_fixB<<<512, 256, 8 * 257 * 4 + 128 * 257 * 4 + 8 * 256 * 4>>>(e0, e1, e2, out_idxf);

    k_lossred<<<1, 256>>>(out_loss);
    k_out<<<T_TOK, 352>>>(b_out, out);
}